// round 12
// baseline (speedup 1.0000x reference)
#include <cuda_runtime.h>
#include <cuda_bf16.h>
#include <math.h>
#include <stdint.h>

#define TT 2048
#define BB 64
#define HH 512
#define GG 2048

typedef unsigned long long u64;

// Scratch (module-load allocated).
__device__ float g_xg[268435456];                       // [T][B][4H] f32 (layer-1 xg)
__device__ float g_h2[67108864];                        // layer-2 H f32 (head input)
__device__ __align__(16) __nv_bfloat16 g_ah[33554432];  // x image hi
__device__ __align__(16) __nv_bfloat16 g_al[33554432];  // x image lo
__device__ __align__(16) __nv_bfloat16 g_wih_h[1048576];   // W_ih1 hi [2048][512-pitch]
__device__ __align__(16) __nv_bfloat16 g_wih_l[1048576];
__device__ __align__(16) __nv_bfloat16 g_wb1[2][64][32][512];   // L1 W_hh tiles
__device__ __align__(16) __nv_bfloat16 g_wb2[2][64][32][1024];  // L2 [W_ih2|W_hh2] tiles
__device__ __align__(16) __nv_bfloat16 g_h1i[2][4][64][512];    // h1 images [split][par4][b][j]
__device__ __align__(16) __nv_bfloat16 g_h2i[2][3][64][512];    // h2 images [split][par3][b][j]
__device__ float g_b2[2048];                            // bih2+bhh2
__device__ unsigned g_f1[64 * 32];                      // per-CTA flags (128B apart)
__device__ unsigned g_f2[64 * 32];

__device__ __forceinline__ float sigm_f(float x) {
    return __fdividef(1.0f, 1.0f + __expf(-x));
}
__device__ __forceinline__ float tanh_f(float x) {
    float ax = fabsf(x);
    float e = __expf(-2.0f * ax);
    float r = __fdividef(1.0f - e, 1.0f + e);
    return copysignf(r, x);
}
__device__ __forceinline__ uint32_t smem_u32(const void* p) {
    uint32_t a;
    asm("{ .reg .u64 t; cvta.to.shared.u64 t, %1; cvt.u32.u64 %0, t; }" : "=r"(a) : "l"(p));
    return a;
}
__device__ __forceinline__ void st_release(unsigned* p, unsigned v) {
    asm volatile("st.release.gpu.global.u32 [%0], %1;" :: "l"(p), "r"(v) : "memory");
}
__device__ __forceinline__ unsigned ld_acquire(unsigned* p) {
    unsigned v;
    asm volatile("ld.acquire.gpu.global.u32 %0, [%1];" : "=r"(v) : "l"(p) : "memory");
    return v;
}

#define LDSM_X4(r0, r1, r2, r3, addr) \
    asm volatile("ldmatrix.sync.aligned.m8n8.x4.shared.b16 {%0,%1,%2,%3}, [%4];" \
        : "=r"(r0), "=r"(r1), "=r"(r2), "=r"(r3) : "r"(addr))
#define LDSM_X2(r0, r1, addr) \
    asm volatile("ldmatrix.sync.aligned.m8n8.x2.shared.b16 {%0,%1}, [%2];" \
        : "=r"(r0), "=r"(r1) : "r"(addr))
#define MMA_BF16(d0, d1, d2, d3, a0, a1, a2, a3, b0, b1) \
    asm volatile("mma.sync.aligned.m16n8k16.row.col.f32.bf16.bf16.f32 " \
        "{%0,%1,%2,%3}, {%4,%5,%6,%7}, {%8,%9}, {%0,%1,%2,%3};" \
        : "+f"(d0), "+f"(d1), "+f"(d2), "+f"(d3) \
        : "r"(a0), "r"(a1), "r"(a2), "r"(a3), "r"(b0), "r"(b1))
#define CP16(dst, src) \
    asm volatile("cp.async.cg.shared.global [%0], [%1], 16;" :: "r"(dst), "l"(src))

// ---------------------------------------------------------------------------
// prep_a: split x into bf16 hi/lo; resets flags (block 0) every replay.
// ---------------------------------------------------------------------------
__global__ __launch_bounds__(256) void prep_a(const float* __restrict__ src, int total)
{
    if (blockIdx.x == 0) {
        if (threadIdx.x < 64) g_f1[threadIdx.x * 32] = 0;
        else if (threadIdx.x < 128) g_f2[(threadIdx.x - 64) * 32] = 0;
    }
    int idx = blockIdx.x * 256 + threadIdx.x;
    if (idx >= total) return;
    float v = src[idx];
    __nv_bfloat16 h = __float2bfloat16(v);
    g_ah[idx] = h;
    g_al[idx] = __float2bfloat16(v - __bfloat162float(h));
}

// ---------------------------------------------------------------------------
// prep_wih: split W_ih1 [2048][256] into bf16 hi/lo at pitch 512.
// ---------------------------------------------------------------------------
__global__ __launch_bounds__(256) void prep_wih(const float* __restrict__ W, int K)
{
    int idx = blockIdx.x * 256 + threadIdx.x;
    int n = idx / K;
    int k = idx - n * K;
    float v = W[idx];
    __nv_bfloat16 h = __float2bfloat16(v);
    g_wih_h[n * 512 + k] = h;
    g_wih_l[n * 512 + k] = __float2bfloat16(v - __bfloat162float(h));
}

// ---------------------------------------------------------------------------
// prep_w: split Whh1 into gate-interleaved tiles g_wb1.
// ---------------------------------------------------------------------------
__global__ __launch_bounds__(256) void prep_w(const float* __restrict__ Whh)
{
    int idx  = blockIdx.x * 256 + threadIdx.x;     // < 524288
    int rg   = idx >> 13;
    int r    = (idx >> 8) & 31;
    int k    = (idx & 255) * 2;
    int wrow = (r & 3) * 512 + rg * 8 + (r >> 2);

    float v0 = __ldg(&Whh[(size_t)wrow * HH + k]);
    float v1 = __ldg(&Whh[(size_t)wrow * HH + k + 1]);
    __nv_bfloat16 h0 = __float2bfloat16(v0);
    __nv_bfloat16 h1 = __float2bfloat16(v1);
    g_wb1[0][rg][r][k]     = h0;
    g_wb1[0][rg][r][k + 1] = h1;
    g_wb1[1][rg][r][k]     = __float2bfloat16(v0 - __bfloat162float(h0));
    g_wb1[1][rg][r][k + 1] = __float2bfloat16(v1 - __bfloat162float(h1));
}

// ---------------------------------------------------------------------------
// prep_w2: concat [W_ih2 | W_hh2] gate-interleaved tiles g_wb2 (K=1024).
// ---------------------------------------------------------------------------
__global__ __launch_bounds__(256) void prep_w2(
    const float* __restrict__ Wih2, const float* __restrict__ Whh2)
{
    int idx = blockIdx.x * 256 + threadIdx.x;      // < 2097152
    int rg  = idx >> 15;
    int r   = (idx >> 10) & 31;
    int k   = idx & 1023;
    int wrow = (r & 3) * 512 + rg * 8 + (r >> 2);
    float v = (k < 512) ? __ldg(&Wih2[(size_t)wrow * 512 + k])
                        : __ldg(&Whh2[(size_t)wrow * 512 + (k - 512)]);
    __nv_bfloat16 h = __float2bfloat16(v);
    g_wb2[0][rg][r][k] = h;
    g_wb2[1][rg][r][k] = __float2bfloat16(v - __bfloat162float(h));
}

__global__ __launch_bounds__(256) void prep_b2(
    const float* __restrict__ bih2, const float* __restrict__ bhh2)
{
    int i = blockIdx.x * 256 + threadIdx.x;
    if (i < 2048) g_b2[i] = bih2[i] + bhh2[i];
}

// ---------------------------------------------------------------------------
// gemm_mma: xg1 = x*W_ih1^T + biases (3-split bf16 mma, K=256). (R9 machinery)
// ---------------------------------------------------------------------------
#define KC 32
#define APB 80
#define REGB (128 * APB)
#define STGB (4 * REGB)
#define GSMEM (2 * STGB)

__global__ __launch_bounds__(256) void gemm_mma(
    const float* __restrict__ bi, const float* __restrict__ bh,
    float* __restrict__ C, int K)
{
    extern __shared__ __align__(16) char gsm[];
    const uint32_t smb = smem_u32(gsm);
    const int tid = threadIdx.x;
    const int wid = tid >> 5, lane = tid & 31;
    const int n0 = blockIdx.x * 128;
    const int m0 = blockIdx.y * 128;
    const int wm = (wid & 1) * 64;
    const int wn = (wid >> 1) * 32;

    auto load_chunk = [&](int c, int s) {
        int kb = c * KC;
        uint32_t base = smb + s * STGB;
        #pragma unroll
        for (int j = 0; j < 8; j++) {
            int u = tid + j * 256;
            int r = u >> 9;
            int e = u & 511;
            int row = e >> 2, q = e & 3;
            const __nv_bfloat16* src;
            if (r == 0)      src = g_ah + (size_t)(m0 + row) * K + kb + q * 8;
            else if (r == 1) src = g_al + (size_t)(m0 + row) * K + kb + q * 8;
            else if (r == 2) src = g_wih_h + (size_t)(n0 + row) * 512 + kb + q * 8;
            else             src = g_wih_l + (size_t)(n0 + row) * 512 + kb + q * 8;
            CP16(base + r * REGB + row * APB + q * 16, src);
        }
        asm volatile("cp.async.commit_group;");
    };

    float acc[4][4][4];
    #pragma unroll
    for (int a = 0; a < 4; a++)
        #pragma unroll
        for (int b = 0; b < 4; b++)
            #pragma unroll
            for (int cix = 0; cix < 4; cix++) acc[a][b][cix] = 0.0f;

    const int NC = K / KC;
    load_chunk(0, 0);
    for (int c = 0; c < NC; c++) {
        if (c + 1 < NC) {
            load_chunk(c + 1, (c + 1) & 1);
            asm volatile("cp.async.wait_group 1;");
        } else {
            asm volatile("cp.async.wait_group 0;");
        }
        __syncthreads();
        uint32_t st = smb + (c & 1) * STGB;
        #pragma unroll
        for (int ks = 0; ks < 2; ks++) {
            uint32_t ko = ks * 32;
            uint32_t Ah[4][4], Al[4][4], Bh[4][2], Bl[4][2];
            #pragma unroll
            for (int f = 0; f < 4; f++) {
                uint32_t ar = st + (uint32_t)(wm + f * 16 + (lane & 15)) * APB
                            + ((lane >> 4) * 16) + ko;
                LDSM_X4(Ah[f][0], Ah[f][1], Ah[f][2], Ah[f][3], ar);
                LDSM_X4(Al[f][0], Al[f][1], Al[f][2], Al[f][3], ar + REGB);
                uint32_t br = st + 2 * REGB + (uint32_t)(wn + f * 8 + (lane & 7)) * APB
                            + (((lane >> 3) & 1) * 16) + ko;
                LDSM_X2(Bh[f][0], Bh[f][1], br);
                LDSM_X2(Bl[f][0], Bl[f][1], br + REGB);
            }
            #pragma unroll
            for (int mf = 0; mf < 4; mf++)
                #pragma unroll
                for (int nf = 0; nf < 4; nf++) {
                    MMA_BF16(acc[mf][nf][0], acc[mf][nf][1], acc[mf][nf][2], acc[mf][nf][3],
                             Ah[mf][0], Ah[mf][1], Ah[mf][2], Ah[mf][3], Bh[nf][0], Bh[nf][1]);
                    MMA_BF16(acc[mf][nf][0], acc[mf][nf][1], acc[mf][nf][2], acc[mf][nf][3],
                             Ah[mf][0], Ah[mf][1], Ah[mf][2], Ah[mf][3], Bl[nf][0], Bl[nf][1]);
                    MMA_BF16(acc[mf][nf][0], acc[mf][nf][1], acc[mf][nf][2], acc[mf][nf][3],
                             Al[mf][0], Al[mf][1], Al[mf][2], Al[mf][3], Bh[nf][0], Bh[nf][1]);
                }
        }
        __syncthreads();
    }

    #pragma unroll
    for (int nf = 0; nf < 4; nf++) {
        int n = n0 + wn + nf * 8 + (lane & 3) * 2;
        float b0 = __ldg(&bi[n]) + __ldg(&bh[n]);
        float b1 = __ldg(&bi[n + 1]) + __ldg(&bh[n + 1]);
        #pragma unroll
        for (int mf = 0; mf < 4; mf++) {
            int m = m0 + wm + mf * 16 + (lane >> 2);
            *(float2*)&C[(size_t)m * GG + n] =
                make_float2(acc[mf][nf][0] + b0, acc[mf][nf][1] + b1);
            *(float2*)&C[(size_t)(m + 8) * GG + n] =
                make_float2(acc[mf][nf][2] + b0, acc[mf][nf][3] + b1);
        }
    }
}

// ---------------------------------------------------------------------------
// Fused 2-layer pipelined recurrence. 128 CTAs:
//   bid<64 : layer 1, rgrp=bid.  M=32 gate rows, N=64 batches, K=512.
//   bid>=64: layer 2, rgrp=bid-64. K=1024 concat [W_ih2|W_hh2]*[h1(t);h2(t-1)].
// Per-CTA release flags; h1 depth-4 images, h2 depth-3; chunked cp.async
// staging double-buffered and pipelined with MMA.
// ---------------------------------------------------------------------------
#define WPB 2064                    // W row pitch bytes (bank-safe)
#define ASPLIT (32 * WPB)           // 66048
#define OFF_BUF (2 * ASPLIT)        // 132096
#define HPB 272                     // chunk-buf row pitch bytes
#define CHB (64 * HPB)              // 17408 per split
#define OFF_D (OFF_BUF + 4 * CHB)   // 201728
#define FSMEM (OFF_D + 32 * 68 * 4) // 210432

__global__ __launch_bounds__(256, 1) void lstm_fused(
    const float* __restrict__ xg1, float* __restrict__ H)
{
    extern __shared__ char smc[];
    const uint32_t smb = smem_u32(smc);
    float* sD = (float*)(smc + OFF_D);

    const int tid  = threadIdx.x;
    const int wid  = tid >> 5;
    const int lane = tid & 31;
    const int isL2 = (blockIdx.x >= 64);
    const int rgrp = blockIdx.x & 63;
    const int j0   = rgrp * 8;

    // Load resident W tiles (both splits), pitch WPB.
    {
        const int kt = isL2 ? 1024 : 512;
        const int rowU4 = kt >> 3;
        const uint4* src = isL2 ? (const uint4*)&g_wb2[0][rgrp][0][0]
                                : (const uint4*)&g_wb1[0][rgrp][0][0];
        const int splitU4 = 64 * 32 * rowU4;       // uint4 stride split0->split1
        const int tot = 2 * 32 * rowU4;
        for (int i = tid; i < tot; i += 256) {
            int s = i / (32 * rowU4);
            int rem = i - s * (32 * rowU4);
            int row = rem / rowU4, q = rem - row * rowU4;
            *(uint4*)(smc + s * ASPLIT + row * WPB + q * 16) =
                __ldg(src + (size_t)s * splitU4 + row * rowU4 + q);
        }
    }

    // MMA addressing (warp tile 16m x 16n; 2 m-warps x 4 n-warps).
    const int wm = (wid & 1) * 16;
    const int wn = (wid >> 1) * 16;
    const uint32_t aBase = smb + (uint32_t)(wm + (lane & 15)) * WPB + ((lane >> 4) * 16);
    const uint32_t bOff  = (uint32_t)(wn + (lane & 7) + ((lane >> 4) << 3)) * HPB
                         + (((lane >> 3) & 1) * 16);

    // Pointwise mapping: u = unit-in-group, bb/bb+32 = two batches.
    const int u  = tid & 7;
    const int bb = tid >> 3;
    float cs0 = 0.0f, cs1 = 0.0f;
    float bz[4];
    if (isL2) {
        #pragma unroll
        for (int g = 0; g < 4; g++) bz[g] = g_b2[g * 512 + j0 + u];
    }
    unsigned* myflag = (isL2 ? g_f2 : g_f1) + rgrp * 32;

    for (int t = 0; t < TT; t++) {
        // L1 xg loads (DRAM latency overlapped with polls).
        float xv[8];
        if (!isL2) {
            const float* xr = xg1 + (size_t)t * BB * GG;
            #pragma unroll
            for (int g = 0; g < 4; g++) {
                xv[g]     = __ldg(xr + (size_t)bb * GG + g * 512 + j0 + u);
                xv[4 + g] = __ldg(xr + (size_t)(bb + 32) * GG + g * 512 + j0 + u);
            }
        }

        const int nch = isL2 ? (t > 0 ? 8 : 4) : (t > 0 ? 4 : 0);
        float a00 = 0.f, a01 = 0.f, a02 = 0.f, a03 = 0.f;
        float a10 = 0.f, a11 = 0.f, a12 = 0.f, a13 = 0.f;

        if (nch) {
            auto pollc = [&](int c, bool bp) {
                if (tid < 16) {
                    unsigned* fp; int tgt;
                    if (!isL2)       { fp = g_f1 + (c * 16 + tid) * 32; tgt = t; }
                    else if (c < 4)  { fp = g_f1 + (c * 16 + tid) * 32; tgt = t + 1; }
                    else             { fp = g_f2 + ((c - 4) * 16 + tid) * 32; tgt = t; }
                    unsigned v;
                    do { v = ld_acquire(fp); } while ((int)v < tgt);
                }
                if (bp && !isL2 && tid >= 32 && tid < 96) {  // h1 depth-4 backpressure
                    int tgt = t - 3;
                    if (tgt > 0) {
                        unsigned* fp = g_f2 + (tid - 32) * 32;
                        unsigned v;
                        do { v = ld_acquire(fp); } while ((int)v < tgt);
                    }
                }
            };
            auto issuec = [&](int c, int bi) {
                const __nv_bfloat16 *sH, *sL;
                if (!isL2) {
                    int par = (t - 1) & 3;
                    sH = &g_h1i[0][par][0][c * 128]; sL = &g_h1i[1][par][0][c * 128];
                } else if (c < 4) {
                    int par = t & 3;
                    sH = &g_h1i[0][par][0][c * 128]; sL = &g_h1i[1][par][0][c * 128];
                } else {
                    int par = (t - 1) % 3;
                    sH = &g_h2i[0][par][0][(c - 4) * 128];
                    sL = &g_h2i[1][par][0][(c - 4) * 128];
                }
                uint32_t db = smb + OFF_BUF + bi * 2 * CHB;
                #pragma unroll
                for (int j = 0; j < 4; j++) {
                    int idx = tid * 4 + j;         // 0..1023
                    int row = idx >> 4, q = idx & 15;
                    uint32_t d = db + row * HPB + q * 16;
                    CP16(d, sH + (size_t)row * 512 + q * 8);
                    CP16(d + CHB, sL + (size_t)row * 512 + q * 8);
                }
                asm volatile("cp.async.commit_group;");
            };
            auto mmac = [&](int c, int bi) {
                uint32_t ab = aBase + (uint32_t)c * 256;
                uint32_t bbs = smb + OFF_BUF + bi * 2 * CHB + bOff;
                #pragma unroll
                for (int ks = 0; ks < 8; ks++) {
                    uint32_t ko = ks * 32;
                    uint32_t ah0, ah1, ah2, ah3, al0, al1, al2, al3;
                    uint32_t bh0, bh1, bh2, bh3, bl0, bl1, bl2, bl3;
                    LDSM_X4(ah0, ah1, ah2, ah3, ab + ko);
                    LDSM_X4(al0, al1, al2, al3, ab + ASPLIT + ko);
                    LDSM_X4(bh0, bh1, bh2, bh3, bbs + ko);
                    LDSM_X4(bl0, bl1, bl2, bl3, bbs + CHB + ko);
                    MMA_BF16(a00, a01, a02, a03, ah0, ah1, ah2, ah3, bh0, bh1);
                    MMA_BF16(a10, a11, a12, a13, ah0, ah1, ah2, ah3, bh2, bh3);
                    MMA_BF16(a00, a01, a02, a03, ah0, ah1, ah2, ah3, bl0, bl1);
                    MMA_BF16(a10, a11, a12, a13, ah0, ah1, ah2, ah3, bl2, bl3);
                    MMA_BF16(a00, a01, a02, a03, al0, al1, al2, al3, bh0, bh1);
                    MMA_BF16(a10, a11, a12, a13, al0, al1, al2, al3, bh2, bh3);
                }
            };

            pollc(0, true);  __syncthreads(); issuec(0, 0);
            pollc(1, false); __syncthreads(); issuec(1, 1);
            for (int i = 0; i < nch; i++) {
                if (i + 2 <= nch - 1) asm volatile("cp.async.wait_group 1;");
                else                  asm volatile("cp.async.wait_group 0;");
                __syncthreads();
                mmac(i, i & 1);
                if (i + 2 < nch) {
                    pollc(i + 2, false);
                    __syncthreads();
                    issuec(i + 2, i & 1);
                }
            }
            // Dump accumulators for pointwise remap.
            {
                int col = wn + (lane & 3) * 2;
                int row = wm + (lane >> 2);
                sD[row * 68 + col]           = a00;
                sD[row * 68 + col + 1]       = a01;
                sD[(row + 8) * 68 + col]     = a02;
                sD[(row + 8) * 68 + col + 1] = a03;
                sD[row * 68 + col + 8]       = a10;
                sD[row * 68 + col + 9]       = a11;
                sD[(row + 8) * 68 + col + 8] = a12;
                sD[(row + 8) * 68 + col + 9] = a13;
            }
            __syncthreads();
        }

        // Fused pointwise for batches bb and bb+32.
        #pragma unroll
        for (int half = 0; half < 2; half++) {
            int b = bb + half * 32;
            float p[4];
            #pragma unroll
            for (int g = 0; g < 4; g++) {
                p[g] = isL2 ? bz[g] : xv[half * 4 + g];
                if (nch) p[g] += sD[(u * 4 + g) * 68 + b];
            }
            float gi = sigm_f(p[0]);
            float gf = sigm_f(p[1]);
            float gz = tanh_f(p[2]);
            float go = sigm_f(p[3]);
            float cc = half ? cs1 : cs0;
            cc = gf * cc + gi * gz;
            if (half) cs1 = cc; else cs0 = cc;
            float hv = go * tanh_f(cc);

            __nv_bfloat16 hi = __float2bfloat16(hv);
            __nv_bfloat16 lo = __float2bfloat16(hv - __bfloat162float(hi));
            if (!isL2) {
                int par = t & 3;
                g_h1i[0][par][b][j0 + u] = hi;
                g_h1i[1][par][b][j0 + u] = lo;
            } else {
                int par = t % 3;
                g_h2i[0][par][b][j0 + u] = hi;
                g_h2i[1][par][b][j0 + u] = lo;
                H[((size_t)t * BB + b) * HH + j0 + u] = hv;
            }
        }

        __syncthreads();
        if (tid == 0) st_release(myflag, (unsigned)(t + 1));
    }
}

// ---------------------------------------------------------------------------
// Output head.
// ---------------------------------------------------------------------------
__global__ __launch_bounds__(256) void out_proj(
    const float* __restrict__ H2, const float* __restrict__ Wout,
    const float* __restrict__ bout, float* __restrict__ out)
{
    int w = (blockIdx.x * blockDim.x + threadIdx.x) >> 5;
    int lane = threadIdx.x & 31;
    if (w >= TT * BB) return;
    const float4* h  = (const float4*)(H2 + (size_t)w * HH);
    const float4* wv = (const float4*)Wout;
    float acc = 0.0f;
    #pragma unroll
    for (int i = lane; i < 128; i += 32) {
        float4 a = __ldg(h + i);
        float4 bv = __ldg(wv + i);
        acc += a.x*bv.x + a.y*bv.y + a.z*bv.z + a.w*bv.w;
    }
    #pragma unroll
    for (int off = 16; off; off >>= 1) acc += __shfl_xor_sync(0xffffffffu, acc, off);
    if (lane == 0) out[w] = 1.0f / (1.0f + expf(-(acc + __ldg(bout))));
}

// ---------------------------------------------------------------------------
extern "C" void kernel_launch(void* const* d_in, const int* in_sizes, int n_in,
                              void* d_out, int out_size)
{
    const float* x     = (const float*)d_in[0];
    const float* Wih1  = (const float*)d_in[1];
    const float* Whh1  = (const float*)d_in[2];
    const float* bih1  = (const float*)d_in[3];
    const float* bhh1  = (const float*)d_in[4];
    const float* Wih2  = (const float*)d_in[5];
    const float* Whh2  = (const float*)d_in[6];
    const float* bih2  = (const float*)d_in[7];
    const float* bhh2  = (const float*)d_in[8];
    const float* Wout  = (const float*)d_in[9];
    const float* bout  = (const float*)d_in[10];
    float* out = (float*)d_out;

    void *xg_p, *h2_p;
    cudaGetSymbolAddress(&xg_p, g_xg);
    cudaGetSymbolAddress(&h2_p, g_h2);
    float* xg = (float*)xg_p;
    float* h2 = (float*)h2_p;

    cudaFuncSetAttribute(lstm_fused, cudaFuncAttributeMaxDynamicSharedMemorySize, FSMEM);
    cudaFuncSetAttribute(gemm_mma, cudaFuncAttributeMaxDynamicSharedMemorySize, GSMEM);

    // Preps (also reset flags each replay via prep_a block 0).
    prep_a<<<(TT * BB * 256 + 255) / 256, 256>>>(x, TT * BB * 256);
    prep_wih<<<(2048 * 256) / 256, 256>>>(Wih1, 256);
    prep_w<<<2048, 256>>>(Whh1);
    prep_w2<<<8192, 256>>>(Wih2, Whh2);
    prep_b2<<<8, 256>>>(bih2, bhh2);

    // Layer-1 input GEMM (xg1 = x * W_ih1^T + biases).
    dim3 ggrid(16, 1024);
    gemm_mma<<<ggrid, 256, GSMEM>>>(bih1, bhh1, xg, 256);

    // Fused pipelined 2-layer recurrence.
    lstm_fused<<<128, 256, FSMEM>>>(xg, h2);

    // Head.
    out_proj<<<(TT * BB * 32 + 255) / 256, 256>>>(h2, Wout, bout, out);
}

// round 13
// speedup vs baseline: 1.2518x; 1.2518x over previous
#include <cuda_runtime.h>
#include <cuda_bf16.h>
#include <math.h>
#include <stdint.h>

#define TT 2048
#define BB 64
#define HH 512
#define GG 2048

typedef unsigned long long u64;

// Scratch (module-load allocated).
__device__ float g_xg[268435456];                    // [T][B][4H] f32 (reused per layer)
__device__ float g_h2[67108864];                     // layer-2 H (head input)
__device__ __align__(16) __nv_bfloat16 g_ah[67108864];  // A image hi (x-split / h1-split)
__device__ __align__(16) __nv_bfloat16 g_al[67108864];  // A image lo
__device__ __align__(16) __nv_bfloat16 g_wih_h[1048576]; // W_ih hi [2048][512]
__device__ __align__(16) __nv_bfloat16 g_wih_l[1048576];
__device__ __align__(16) __nv_bfloat16 g_wb[2][64][32][512];      // [split][jgrp][row][k]
__device__ __align__(16) __nv_bfloat16 g_hb[2][3][2][32][512];    // [split][par3][bh][b][j]
__device__ unsigned g_qf[128 * 32];                  // per-CTA flags (128B apart)

__device__ __forceinline__ float sigm_f(float x) {
    return __fdividef(1.0f, 1.0f + __expf(-x));
}
__device__ __forceinline__ float tanh_f(float x) {
    float ax = fabsf(x);
    float e = __expf(-2.0f * ax);
    float r = __fdividef(1.0f - e, 1.0f + e);
    return copysignf(r, x);
}
__device__ __forceinline__ uint32_t smem_u32(const void* p) {
    uint32_t a;
    asm("{ .reg .u64 t; cvta.to.shared.u64 t, %1; cvt.u32.u64 %0, t; }" : "=r"(a) : "l"(p));
    return a;
}
__device__ __forceinline__ void st_release(unsigned* p, unsigned v) {
    asm volatile("st.release.gpu.global.u32 [%0], %1;" :: "l"(p), "r"(v) : "memory");
}
__device__ __forceinline__ unsigned ld_acquire(unsigned* p) {
    unsigned v;
    asm volatile("ld.acquire.gpu.global.u32 %0, [%1];" : "=r"(v) : "l"(p) : "memory");
    return v;
}

#define LDSM_X4(r0, r1, r2, r3, addr) \
    asm volatile("ldmatrix.sync.aligned.m8n8.x4.shared.b16 {%0,%1,%2,%3}, [%4];" \
        : "=r"(r0), "=r"(r1), "=r"(r2), "=r"(r3) : "r"(addr))
#define LDSM_X2(r0, r1, addr) \
    asm volatile("ldmatrix.sync.aligned.m8n8.x2.shared.b16 {%0,%1}, [%2];" \
        : "=r"(r0), "=r"(r1) : "r"(addr))
#define MMA_BF16(d0, d1, d2, d3, a0, a1, a2, a3, b0, b1) \
    asm volatile("mma.sync.aligned.m16n8k16.row.col.f32.bf16.bf16.f32 " \
        "{%0,%1,%2,%3}, {%4,%5,%6,%7}, {%8,%9}, {%0,%1,%2,%3};" \
        : "+f"(d0), "+f"(d1), "+f"(d2), "+f"(d3) \
        : "r"(a0), "r"(a1), "r"(a2), "r"(a3), "r"(b0), "r"(b1))
#define CP16(dst, src) \
    asm volatile("cp.async.cg.shared.global [%0], [%1], 16;" :: "r"(dst), "l"(src))

// ---------------------------------------------------------------------------
// prep_a: split f32 array into bf16 hi/lo images; resets the 128 per-CTA
// flags (block 0) so every graph replay starts from a clean sync state.
// ---------------------------------------------------------------------------
__global__ __launch_bounds__(256) void prep_a(const float* __restrict__ src, int total)
{
    if (blockIdx.x == 0 && threadIdx.x < 128) g_qf[threadIdx.x * 32] = 0;
    int idx = blockIdx.x * 256 + threadIdx.x;
    if (idx >= total) return;
    float v = src[idx];
    __nv_bfloat16 h = __float2bfloat16(v);
    g_ah[idx] = h;
    g_al[idx] = __float2bfloat16(v - __bfloat162float(h));
}

// ---------------------------------------------------------------------------
// prep_wih: split W_ih [2048][K] f32 into bf16 hi/lo at fixed pitch 512.
// ---------------------------------------------------------------------------
__global__ __launch_bounds__(256) void prep_wih(const float* __restrict__ W, int K)
{
    int idx = blockIdx.x * 256 + threadIdx.x;
    int n = idx / K;
    int k = idx - n * K;
    float v = W[idx];
    __nv_bfloat16 h = __float2bfloat16(v);
    g_wih_h[n * 512 + k] = h;
    g_wih_l[n * 512 + k] = __float2bfloat16(v - __bfloat162float(h));
}

// ---------------------------------------------------------------------------
// gemm_mma: C[M x 2048] = A[M x K]*W[2048 x K]^T + bi + bh (3-split bf16 mma).
// CTA tile 128x128, 8 warps (64x32), K-chunk 32, cp.async 2-stage. (R9)
// ---------------------------------------------------------------------------
#define KC 32
#define APB 80
#define REGB (128 * APB)
#define STGB (4 * REGB)
#define GSMEM (2 * STGB)

__global__ __launch_bounds__(256) void gemm_mma(
    const float* __restrict__ bi, const float* __restrict__ bh,
    float* __restrict__ C, int K)
{
    extern __shared__ __align__(16) char gsm[];
    const uint32_t smb = smem_u32(gsm);
    const int tid = threadIdx.x;
    const int wid = tid >> 5, lane = tid & 31;
    const int n0 = blockIdx.x * 128;
    const int m0 = blockIdx.y * 128;
    const int wm = (wid & 1) * 64;
    const int wn = (wid >> 1) * 32;

    auto load_chunk = [&](int c, int s) {
        int kb = c * KC;
        uint32_t base = smb + s * STGB;
        #pragma unroll
        for (int j = 0; j < 8; j++) {
            int u = tid + j * 256;
            int r = u >> 9;
            int e = u & 511;
            int row = e >> 2, q = e & 3;
            const __nv_bfloat16* src;
            if (r == 0)      src = g_ah + (size_t)(m0 + row) * K + kb + q * 8;
            else if (r == 1) src = g_al + (size_t)(m0 + row) * K + kb + q * 8;
            else if (r == 2) src = g_wih_h + (size_t)(n0 + row) * 512 + kb + q * 8;
            else             src = g_wih_l + (size_t)(n0 + row) * 512 + kb + q * 8;
            CP16(base + r * REGB + row * APB + q * 16, src);
        }
        asm volatile("cp.async.commit_group;");
    };

    float acc[4][4][4];
    #pragma unroll
    for (int a = 0; a < 4; a++)
        #pragma unroll
        for (int b = 0; b < 4; b++)
            #pragma unroll
            for (int cix = 0; cix < 4; cix++) acc[a][b][cix] = 0.0f;

    const int NC = K / KC;
    load_chunk(0, 0);
    for (int c = 0; c < NC; c++) {
        if (c + 1 < NC) {
            load_chunk(c + 1, (c + 1) & 1);
            asm volatile("cp.async.wait_group 1;");
        } else {
            asm volatile("cp.async.wait_group 0;");
        }
        __syncthreads();
        uint32_t st = smb + (c & 1) * STGB;
        #pragma unroll
        for (int ks = 0; ks < 2; ks++) {
            uint32_t ko = ks * 32;
            uint32_t Ah[4][4], Al[4][4], Bh[4][2], Bl[4][2];
            #pragma unroll
            for (int f = 0; f < 4; f++) {
                uint32_t ar = st + (uint32_t)(wm + f * 16 + (lane & 15)) * APB
                            + ((lane >> 4) * 16) + ko;
                LDSM_X4(Ah[f][0], Ah[f][1], Ah[f][2], Ah[f][3], ar);
                LDSM_X4(Al[f][0], Al[f][1], Al[f][2], Al[f][3], ar + REGB);
                uint32_t br = st + 2 * REGB + (uint32_t)(wn + f * 8 + (lane & 7)) * APB
                            + (((lane >> 3) & 1) * 16) + ko;
                LDSM_X2(Bh[f][0], Bh[f][1], br);
                LDSM_X2(Bl[f][0], Bl[f][1], br + REGB);
            }
            #pragma unroll
            for (int mf = 0; mf < 4; mf++)
                #pragma unroll
                for (int nf = 0; nf < 4; nf++) {
                    MMA_BF16(acc[mf][nf][0], acc[mf][nf][1], acc[mf][nf][2], acc[mf][nf][3],
                             Ah[mf][0], Ah[mf][1], Ah[mf][2], Ah[mf][3], Bh[nf][0], Bh[nf][1]);
                    MMA_BF16(acc[mf][nf][0], acc[mf][nf][1], acc[mf][nf][2], acc[mf][nf][3],
                             Ah[mf][0], Ah[mf][1], Ah[mf][2], Ah[mf][3], Bl[nf][0], Bl[nf][1]);
                    MMA_BF16(acc[mf][nf][0], acc[mf][nf][1], acc[mf][nf][2], acc[mf][nf][3],
                             Al[mf][0], Al[mf][1], Al[mf][2], Al[mf][3], Bh[nf][0], Bh[nf][1]);
                }
        }
        __syncthreads();
    }

    #pragma unroll
    for (int nf = 0; nf < 4; nf++) {
        int n = n0 + wn + nf * 8 + (lane & 3) * 2;
        float b0 = __ldg(&bi[n]) + __ldg(&bh[n]);
        float b1 = __ldg(&bi[n + 1]) + __ldg(&bh[n + 1]);
        #pragma unroll
        for (int mf = 0; mf < 4; mf++) {
            int m = m0 + wm + mf * 16 + (lane >> 2);
            *(float2*)&C[(size_t)m * GG + n] =
                make_float2(acc[mf][nf][0] + b0, acc[mf][nf][1] + b1);
            *(float2*)&C[(size_t)(m + 8) * GG + n] =
                make_float2(acc[mf][nf][2] + b0, acc[mf][nf][3] + b1);
        }
    }
}

// ---------------------------------------------------------------------------
// prep_w: split Whh into bf16 hi/lo with gate-interleaved row ordering.
// ---------------------------------------------------------------------------
__global__ __launch_bounds__(256) void prep_w(const float* __restrict__ Whh)
{
    int idx  = blockIdx.x * 256 + threadIdx.x;
    int jgrp = idx >> 13;
    int r    = (idx >> 8) & 31;
    int k    = (idx & 255) * 2;
    int wrow = (r & 3) * 512 + jgrp * 8 + (r >> 2);

    float v0 = __ldg(&Whh[(size_t)wrow * HH + k]);
    float v1 = __ldg(&Whh[(size_t)wrow * HH + k + 1]);
    __nv_bfloat16 h0 = __float2bfloat16(v0);
    __nv_bfloat16 h1 = __float2bfloat16(v1);
    g_wb[0][jgrp][r][k]     = h0;
    g_wb[0][jgrp][r][k + 1] = h1;
    g_wb[1][jgrp][r][k]     = __float2bfloat16(v0 - __bfloat162float(h0));
    g_wb[1][jgrp][r][k + 1] = __float2bfloat16(v1 - __bfloat162float(h1));
}

// ---------------------------------------------------------------------------
// Persistent warp-MMA recurrence (R11 base). Per-CTA release flags; chunk ck
// polls ONLY its own quartile's 16 producer flags, so staging/MMA of early
// quartiles overlaps the skew of later ones. Triple-buffered h images.
// 128 CTAs: jgrp(64) x bh(2), 256 threads.
// ---------------------------------------------------------------------------
#define NCTA 128
#define PITCH 520
#define WBLK (32 * PITCH * 2)
#define OFF_W 0
#define OFF_H (2 * WBLK)
#define OFF_D (4 * WBLK)
#define REC_SMEM (OFF_D + 32 * 33 * 4)

__global__ __launch_bounds__(256, 1) void lstm_rec(
    const float* __restrict__ xg, float* __restrict__ H, int isL2, unsigned qbase)
{
    extern __shared__ char smc[];
    const uint32_t smb = smem_u32(smc);
    float* sD = (float*)(smc + OFF_D);

    const int tid  = threadIdx.x;
    const int wid  = tid >> 5;
    const int lane = tid & 31;
    const int jgrp = blockIdx.x >> 1;
    const int bh   = blockIdx.x & 1;
    const int j0   = jgrp * 8;
    unsigned* myflag = &g_qf[(bh * 64 + jgrp) * 32];

    // Resident W tiles (hi + lo), padded rows.
    {
        uint4* dst = (uint4*)smc;
        #pragma unroll 2
        for (int s = 0; s < 2; s++) {
            const uint4* src = (const uint4*)&g_wb[s][jgrp][0][0];
            uint4* d = dst + s * (WBLK / 16);
            for (int i = tid; i < 2048; i += 256) {
                int row = i >> 6, c = i & 63;
                d[row * 65 + c] = __ldg(src + i);
            }
        }
    }

    const int arow = lane & 15;
    const uint32_t akoff = (lane >> 4) * 16;
    const int brow = lane & 7;
    const uint32_t bkoff = ((lane >> 3) & 1) * 16;
    const int m0 = (wid & 1) * 16;
    const int n0 = (wid >> 1) * 8;

    const uint32_t aHi0 = smb + OFF_W + (uint32_t)(m0 + arow) * (PITCH * 2) + akoff;
    const uint32_t aLo0 = aHi0 + WBLK;
    const uint32_t bHi0 = smb + OFF_H + (uint32_t)(n0 + brow) * (PITCH * 2) + bkoff;
    const uint32_t bLo0 = bHi0 + WBLK;

    const int u  = tid & 7;
    const int b  = tid >> 3;
    const int gb = bh * 32 + b;
    float c = 0.0f;

    for (int t = 0; t < TT; t++) {
        // xg prefetch first (DRAM latency overlapped with polls).
        float xv0 = __ldg(&xg[((size_t)t * BB + gb) * GG +        j0 + u]);
        float xv1 = __ldg(&xg[((size_t)t * BB + gb) * GG +  512 + j0 + u]);
        float xv2 = __ldg(&xg[((size_t)t * BB + gb) * GG + 1024 + j0 + u]);
        float xv3 = __ldg(&xg[((size_t)t * BB + gb) * GG + 1536 + j0 + u]);

        if (t > 0) {
            int par = (t - 1) % 3;
            const __nv_bfloat16* baseH = &g_hb[0][par][bh][0][0];
            const __nv_bfloat16* baseL = &g_hb[1][par][bh][0][0];
            const unsigned tgt = qbase + (unsigned)t;

            // Poll only quartile ck's 16 producer flags (16 threads parallel).
            auto pollq = [&](int ck) {
                if (tid < 16) {
                    unsigned* fp = &g_qf[(bh * 64 + ck * 16 + tid) * 32];
                    unsigned v;
                    do { v = ld_acquire(fp); } while ((int)(v - tgt) < 0);
                }
            };
            // Stage chunk ck (128 k of both splits) into its column range.
            auto issuec = [&](int ck) {
                #pragma unroll
                for (int j = 0; j < 2; j++) {
                    int i = tid * 2 + j;          // 0..511
                    int row = i >> 4, q = i & 15;
                    uint32_t dst = smb + OFF_H + (uint32_t)row * (PITCH * 2)
                                 + (uint32_t)(ck * 16 + q) * 16;
                    CP16(dst, baseH + row * 512 + ck * 128 + q * 8);
                    CP16(dst + WBLK, baseL + row * 512 + ck * 128 + q * 8);
                }
                asm volatile("cp.async.commit_group;");
            };

            pollq(0); __syncthreads(); issuec(0);
            pollq(1); __syncthreads(); issuec(1);

            float d0 = 0.f, d1 = 0.f, d2 = 0.f, d3 = 0.f;
            #pragma unroll
            for (int ck = 0; ck < 4; ck++) {
                if (ck < 3) asm volatile("cp.async.wait_group 1;");
                else        asm volatile("cp.async.wait_group 0;");
                __syncthreads();
                #pragma unroll
                for (int ks = 0; ks < 8; ks++) {
                    uint32_t ko = (uint32_t)(ck * 8 + ks) * 32;
                    uint32_t ah0, ah1, ah2, ah3, al0, al1, al2, al3;
                    uint32_t bhr0, bhr1, blr0, blr1;
                    LDSM_X4(ah0, ah1, ah2, ah3, aHi0 + ko);
                    LDSM_X4(al0, al1, al2, al3, aLo0 + ko);
                    LDSM_X2(bhr0, bhr1, bHi0 + ko);
                    LDSM_X2(blr0, blr1, bLo0 + ko);
                    MMA_BF16(d0, d1, d2, d3, ah0, ah1, ah2, ah3, bhr0, bhr1);
                    MMA_BF16(d0, d1, d2, d3, ah0, ah1, ah2, ah3, blr0, blr1);
                    MMA_BF16(d0, d1, d2, d3, al0, al1, al2, al3, bhr0, bhr1);
                }
                if (ck + 2 < 4) {
                    pollq(ck + 2);
                    __syncthreads();
                    issuec(ck + 2);
                }
            }
            {
                int gid = lane >> 2, tig = lane & 3;
                int row = m0 + gid, col = n0 + tig * 2;
                sD[row * 33 + col]           = d0;
                sD[row * 33 + col + 1]       = d1;
                sD[(row + 8) * 33 + col]     = d2;
                sD[(row + 8) * 33 + col + 1] = d3;
            }
            __syncthreads();
        }

        // Fused pointwise: gates of unit u, batch b (tile row = u*4+g).
        {
            float p0 = xv0, p1 = xv1, p2 = xv2, p3 = xv3;
            if (t > 0) {
                p0 += sD[(u * 4 + 0) * 33 + b];
                p1 += sD[(u * 4 + 1) * 33 + b];
                p2 += sD[(u * 4 + 2) * 33 + b];
                p3 += sD[(u * 4 + 3) * 33 + b];
            }
            float gi = sigm_f(p0);
            float gf = sigm_f(p1);
            float gz = tanh_f(p2);
            float go = sigm_f(p3);
            c = gf * c + gi * gz;
            float hv = go * tanh_f(c);

            __nv_bfloat16 hi = __float2bfloat16(hv);
            __nv_bfloat16 lo = __float2bfloat16(hv - __bfloat162float(hi));
            int par = t % 3;
            g_hb[0][par][bh][b][j0 + u] = hi;
            g_hb[1][par][bh][b][j0 + u] = lo;
            if (isL2) {
                H[((size_t)t * BB + gb) * HH + j0 + u] = hv;   // out_proj input
            } else {
                size_t aidx = ((size_t)t * BB + gb) * HH + j0 + u;
                g_ah[aidx] = hi;                               // layer-2 GEMM A image
                g_al[aidx] = lo;
            }
        }

        // Publish this CTA's 8 units of h(t) (release after syncthreads).
        __syncthreads();
        if (tid == 0) st_release(myflag, qbase + (unsigned)(t + 1));
    }
}

// ---------------------------------------------------------------------------
// Output head.
// ---------------------------------------------------------------------------
__global__ __launch_bounds__(256) void out_proj(
    const float* __restrict__ H2, const float* __restrict__ Wout,
    const float* __restrict__ bout, float* __restrict__ out)
{
    int w = (blockIdx.x * blockDim.x + threadIdx.x) >> 5;
    int lane = threadIdx.x & 31;
    if (w >= TT * BB) return;
    const float4* h  = (const float4*)(H2 + (size_t)w * HH);
    const float4* wv = (const float4*)Wout;
    float acc = 0.0f;
    #pragma unroll
    for (int i = lane; i < 128; i += 32) {
        float4 a = __ldg(h + i);
        float4 bb = __ldg(wv + i);
        acc += a.x*bb.x + a.y*bb.y + a.z*bb.z + a.w*bb.w;
    }
    #pragma unroll
    for (int off = 16; off; off >>= 1) acc += __shfl_xor_sync(0xffffffffu, acc, off);
    if (lane == 0) out[w] = 1.0f / (1.0f + expf(-(acc + __ldg(bout))));
}

// ---------------------------------------------------------------------------
extern "C" void kernel_launch(void* const* d_in, const int* in_sizes, int n_in,
                              void* d_out, int out_size)
{
    const float* x     = (const float*)d_in[0];
    const float* Wih1  = (const float*)d_in[1];
    const float* Whh1  = (const float*)d_in[2];
    const float* bih1  = (const float*)d_in[3];
    const float* bhh1  = (const float*)d_in[4];
    const float* Wih2  = (const float*)d_in[5];
    const float* Whh2  = (const float*)d_in[6];
    const float* bih2  = (const float*)d_in[7];
    const float* bhh2  = (const float*)d_in[8];
    const float* Wout  = (const float*)d_in[9];
    const float* bout  = (const float*)d_in[10];
    float* out = (float*)d_out;

    void *xg_p, *h2_p;
    cudaGetSymbolAddress(&xg_p, g_xg);
    cudaGetSymbolAddress(&h2_p, g_h2);
    float* xg = (float*)xg_p;
    float* h2 = (float*)h2_p;

    cudaFuncSetAttribute(lstm_rec, cudaFuncAttributeMaxDynamicSharedMemorySize, REC_SMEM);
    cudaFuncSetAttribute(gemm_mma, cudaFuncAttributeMaxDynamicSharedMemorySize, GSMEM);

    dim3 ggrid(16, 1024);   // (N/128, M/128)

    // Layer 1
    prep_a<<<(TT * BB * 256 + 255) / 256, 256>>>(x, TT * BB * 256);  // also resets g_qf
    prep_wih<<<(2048 * 256) / 256, 256>>>(Wih1, 256);
    gemm_mma<<<ggrid, 256, GSMEM>>>(bih1, bhh1, xg, 256);
    prep_w<<<2048, 256>>>(Whh1);
    lstm_rec<<<NCTA, 256, REC_SMEM>>>(xg, h2, 0, 0u);        // writes g_ah/g_al
    // Layer 2 (xg reused); flags continue from TT per CTA
    prep_wih<<<(2048 * 512) / 256, 256>>>(Wih2, 512);
    gemm_mma<<<ggrid, 256, GSMEM>>>(bih2, bhh2, xg, 512);
    prep_w<<<2048, 256>>>(Whh2);
    lstm_rec<<<NCTA, 256, REC_SMEM>>>(xg, h2, 1, (unsigned)TT);  // writes f32 H
    // Head
    out_proj<<<(TT * BB * 32 + 255) / 256, 256>>>(h2, Wout, bout, out);
}

// round 15
// speedup vs baseline: 1.4429x; 1.1526x over previous
#include <cuda_runtime.h>
#include <cuda_bf16.h>
#include <math.h>
#include <stdint.h>

#define TT 2048
#define BB 64
#define HH 512
#define GG 2048

typedef unsigned long long u64;

// Scratch (module-load allocated).
__device__ float g_xg[268435456];                    // [T][B][4H] f32 layer-1 xg
__device__ float g_xg2[268435456];                   // [T][B][4H] f32 layer-2 xg (in-rec)
__device__ float g_h2[67108864];                     // layer-2 H (head input)
__device__ __align__(16) __nv_bfloat16 g_ah[33554432];  // x image hi [T*B*256]
__device__ __align__(16) __nv_bfloat16 g_al[33554432];  // x image lo
__device__ __align__(16) __nv_bfloat16 g_wih_h[1048576]; // W_ih1 hi [2048][512-pitch]
__device__ __align__(16) __nv_bfloat16 g_wih_l[1048576];
__device__ __align__(16) __nv_bfloat16 g_wA[2097152];   // Whh1 tiles [split][jgrp][32][512]
__device__ __align__(16) __nv_bfloat16 g_wB[2097152];   // Whh2 tiles
__device__ __align__(16) __nv_bfloat16 g_wC[2097152];   // Wih2 tiles
__device__ __align__(16) __nv_bfloat16 g_hb[2][3][2][32][512];   // [split][par3][bh][b][j]
__device__ float g_b2[2048];                         // bih2+bhh2
__device__ unsigned g_qf[8 * 32];                    // quartile counters (128B apart)

__device__ __forceinline__ float sigm_f(float x) {
    return __fdividef(1.0f, 1.0f + __expf(-x));
}
__device__ __forceinline__ float tanh_f(float x) {
    float ax = fabsf(x);
    float e = __expf(-2.0f * ax);
    float r = __fdividef(1.0f - e, 1.0f + e);
    return copysignf(r, x);
}
__device__ __forceinline__ uint32_t smem_u32(const void* p) {
    uint32_t a;
    asm("{ .reg .u64 t; cvta.to.shared.u64 t, %1; cvt.u32.u64 %0, t; }" : "=r"(a) : "l"(p));
    return a;
}
__device__ __forceinline__ void atom_add_release(unsigned* p) {
    unsigned o;
    asm volatile("atom.acq_rel.gpu.global.add.u32 %0, [%1], %2;"
                 : "=r"(o) : "l"(p), "r"(1u) : "memory");
}
__device__ __forceinline__ unsigned ld_acquire(unsigned* p) {
    unsigned v;
    asm volatile("ld.acquire.gpu.global.u32 %0, [%1];" : "=r"(v) : "l"(p) : "memory");
    return v;
}

#define LDSM_X4(r0, r1, r2, r3, addr) \
    asm volatile("ldmatrix.sync.aligned.m8n8.x4.shared.b16 {%0,%1,%2,%3}, [%4];" \
        : "=r"(r0), "=r"(r1), "=r"(r2), "=r"(r3) : "r"(addr))
#define LDSM_X2(r0, r1, addr) \
    asm volatile("ldmatrix.sync.aligned.m8n8.x2.shared.b16 {%0,%1}, [%2];" \
        : "=r"(r0), "=r"(r1) : "r"(addr))
#define MMA_BF16(d0, d1, d2, d3, a0, a1, a2, a3, b0, b1) \
    asm volatile("mma.sync.aligned.m16n8k16.row.col.f32.bf16.bf16.f32 " \
        "{%0,%1,%2,%3}, {%4,%5,%6,%7}, {%8,%9}, {%0,%1,%2,%3};" \
        : "+f"(d0), "+f"(d1), "+f"(d2), "+f"(d3) \
        : "r"(a0), "r"(a1), "r"(a2), "r"(a3), "r"(b0), "r"(b1))
#define CP16(dst, src) \
    asm volatile("cp.async.cg.shared.global [%0], [%1], 16;" :: "r"(dst), "l"(src))

// ---------------------------------------------------------------------------
// prep_a: split x into bf16 hi/lo images; resets the 8 quartile counters
// (block 0) so every graph replay starts from a clean sync state.
// ---------------------------------------------------------------------------
__global__ __launch_bounds__(256) void prep_a(const float* __restrict__ src, int total)
{
    if (blockIdx.x == 0 && threadIdx.x < 8) g_qf[threadIdx.x * 32] = 0;
    int idx = blockIdx.x * 256 + threadIdx.x;
    if (idx >= total) return;
    float v = src[idx];
    __nv_bfloat16 h = __float2bfloat16(v);
    g_ah[idx] = h;
    g_al[idx] = __float2bfloat16(v - __bfloat162float(h));
}

// ---------------------------------------------------------------------------
// prep_wih: split W_ih1 [2048][K] f32 into bf16 hi/lo at fixed pitch 512.
// ---------------------------------------------------------------------------
__global__ __launch_bounds__(256) void prep_wih(const float* __restrict__ W, int K)
{
    int idx = blockIdx.x * 256 + threadIdx.x;
    int n = idx / K;
    int k = idx - n * K;
    float v = W[idx];
    __nv_bfloat16 h = __float2bfloat16(v);
    g_wih_h[n * 512 + k] = h;
    g_wih_l[n * 512 + k] = __float2bfloat16(v - __bfloat162float(h));
}

// ---------------------------------------------------------------------------
// prep_wsplit: split a [2048][512] weight into bf16 hi/lo gate-interleaved
// tiles at dst ([split][jgrp][32][512] flattened).
// ---------------------------------------------------------------------------
__global__ __launch_bounds__(256) void prep_wsplit(
    const float* __restrict__ W, __nv_bfloat16* __restrict__ dst)
{
    int idx  = blockIdx.x * 256 + threadIdx.x;     // < 524288
    int jgrp = idx >> 13;
    int r    = (idx >> 8) & 31;
    int k    = (idx & 255) * 2;
    int wrow = (r & 3) * 512 + jgrp * 8 + (r >> 2);

    float v0 = __ldg(&W[(size_t)wrow * HH + k]);
    float v1 = __ldg(&W[(size_t)wrow * HH + k + 1]);
    __nv_bfloat16 h0 = __float2bfloat16(v0);
    __nv_bfloat16 h1 = __float2bfloat16(v1);
    size_t base = ((size_t)jgrp * 32 + r) * 512 + k;
    dst[base]               = h0;
    dst[base + 1]           = h1;
    dst[1048576 + base]     = __float2bfloat16(v0 - __bfloat162float(h0));
    dst[1048576 + base + 1] = __float2bfloat16(v1 - __bfloat162float(h1));
}

__global__ __launch_bounds__(256) void prep_b2(
    const float* __restrict__ bih2, const float* __restrict__ bhh2)
{
    int i = blockIdx.x * 256 + threadIdx.x;
    if (i < 2048) g_b2[i] = bih2[i] + bhh2[i];
}

// ---------------------------------------------------------------------------
// gemm_mma: xg1 = x*W_ih1^T + biases (3-split bf16 mma, K=256). (R9 machinery)
// ---------------------------------------------------------------------------
#define KC 32
#define APB 80
#define REGB (128 * APB)
#define STGB (4 * REGB)
#define GSMEM (2 * STGB)

__global__ __launch_bounds__(256) void gemm_mma(
    const float* __restrict__ bi, const float* __restrict__ bh,
    float* __restrict__ C, int K)
{
    extern __shared__ __align__(16) char gsm[];
    const uint32_t smb = smem_u32(gsm);
    const int tid = threadIdx.x;
    const int wid = tid >> 5, lane = tid & 31;
    const int n0 = blockIdx.x * 128;
    const int m0 = blockIdx.y * 128;
    const int wm = (wid & 1) * 64;
    const int wn = (wid >> 1) * 32;

    auto load_chunk = [&](int c, int s) {
        int kb = c * KC;
        uint32_t base = smb + s * STGB;
        #pragma unroll
        for (int j = 0; j < 8; j++) {
            int u = tid + j * 256;
            int r = u >> 9;
            int e = u & 511;
            int row = e >> 2, q = e & 3;
            const __nv_bfloat16* src;
            if (r == 0)      src = g_ah + (size_t)(m0 + row) * K + kb + q * 8;
            else if (r == 1) src = g_al + (size_t)(m0 + row) * K + kb + q * 8;
            else if (r == 2) src = g_wih_h + (size_t)(n0 + row) * 512 + kb + q * 8;
            else             src = g_wih_l + (size_t)(n0 + row) * 512 + kb + q * 8;
            CP16(base + r * REGB + row * APB + q * 16, src);
        }
        asm volatile("cp.async.commit_group;");
    };

    float acc[4][4][4];
    #pragma unroll
    for (int a = 0; a < 4; a++)
        #pragma unroll
        for (int b = 0; b < 4; b++)
            #pragma unroll
            for (int cix = 0; cix < 4; cix++) acc[a][b][cix] = 0.0f;

    const int NC = K / KC;
    load_chunk(0, 0);
    for (int c = 0; c < NC; c++) {
        if (c + 1 < NC) {
            load_chunk(c + 1, (c + 1) & 1);
            asm volatile("cp.async.wait_group 1;");
        } else {
            asm volatile("cp.async.wait_group 0;");
        }
        __syncthreads();
        uint32_t st = smb + (c & 1) * STGB;
        #pragma unroll
        for (int ks = 0; ks < 2; ks++) {
            uint32_t ko = ks * 32;
            uint32_t Ah[4][4], Al[4][4], Bh[4][2], Bl[4][2];
            #pragma unroll
            for (int f = 0; f < 4; f++) {
                uint32_t ar = st + (uint32_t)(wm + f * 16 + (lane & 15)) * APB
                            + ((lane >> 4) * 16) + ko;
                LDSM_X4(Ah[f][0], Ah[f][1], Ah[f][2], Ah[f][3], ar);
                LDSM_X4(Al[f][0], Al[f][1], Al[f][2], Al[f][3], ar + REGB);
                uint32_t br = st + 2 * REGB + (uint32_t)(wn + f * 8 + (lane & 7)) * APB
                            + (((lane >> 3) & 1) * 16) + ko;
                LDSM_X2(Bh[f][0], Bh[f][1], br);
                LDSM_X2(Bl[f][0], Bl[f][1], br + REGB);
            }
            #pragma unroll
            for (int mf = 0; mf < 4; mf++)
                #pragma unroll
                for (int nf = 0; nf < 4; nf++) {
                    MMA_BF16(acc[mf][nf][0], acc[mf][nf][1], acc[mf][nf][2], acc[mf][nf][3],
                             Ah[mf][0], Ah[mf][1], Ah[mf][2], Ah[mf][3], Bh[nf][0], Bh[nf][1]);
                    MMA_BF16(acc[mf][nf][0], acc[mf][nf][1], acc[mf][nf][2], acc[mf][nf][3],
                             Ah[mf][0], Ah[mf][1], Ah[mf][2], Ah[mf][3], Bl[nf][0], Bl[nf][1]);
                    MMA_BF16(acc[mf][nf][0], acc[mf][nf][1], acc[mf][nf][2], acc[mf][nf][3],
                             Al[mf][0], Al[mf][1], Al[mf][2], Al[mf][3], Bh[nf][0], Bh[nf][1]);
                }
        }
        __syncthreads();
    }

    #pragma unroll
    for (int nf = 0; nf < 4; nf++) {
        int n = n0 + wn + nf * 8 + (lane & 3) * 2;
        float b0 = __ldg(&bi[n]) + __ldg(&bh[n]);
        float b1 = __ldg(&bi[n + 1]) + __ldg(&bh[n + 1]);
        #pragma unroll
        for (int mf = 0; mf < 4; mf++) {
            int m = m0 + wm + mf * 16 + (lane >> 2);
            *(float2*)&C[(size_t)m * GG + n] =
                make_float2(acc[mf][nf][0] + b0, acc[mf][nf][1] + b1);
            *(float2*)&C[(size_t)(m + 8) * GG + n] =
                make_float2(acc[mf][nf][2] + b0, acc[mf][nf][3] + b1);
        }
    }
}

// ---------------------------------------------------------------------------
// Persistent warp-MMA recurrence (R11 protocol, verbatim) with optional FUSED
// layer-2 input GEMM: when fuse=1, W_ih2 tiles are also SMEM-resident and each
// step additionally computes xg2(t-1) = W_ih2*h1(t-1) (+biases via accumulator
// init) from the ALREADY-STAGED h image, writing g_xg2. Epilogue covers t=TT-1.
// 128 CTAs: jgrp(64) x bh(2), 256 threads.
// ---------------------------------------------------------------------------
#define NCTA 128
#define PITCH 520
#define WBLK (32 * PITCH * 2)
#define OFF_W 0
#define OFF_H (2 * WBLK)
#define OFF_D (4 * WBLK)
#define OFF_W2 (OFF_D + 32 * 33 * 4)       // 137344
#define REC_SMEM (OFF_W2)                  // non-fused launch
#define REC_SMEM_F (OFF_W2 + 2 * WBLK)     // 203904 (fused launch)

__global__ __launch_bounds__(256, 1) void lstm_rec(
    const __nv_bfloat16* __restrict__ wt,   // recurrent W tiles
    const __nv_bfloat16* __restrict__ w2t,  // W_ih2 tiles (fuse only)
    const float* __restrict__ xg, float* __restrict__ xg2,
    float* __restrict__ H, int isL2, int fuse, unsigned qbase)
{
    extern __shared__ char smc[];
    const uint32_t smb = smem_u32(smc);
    float* sD = (float*)(smc + OFF_D);

    const int tid  = threadIdx.x;
    const int wid  = tid >> 5;
    const int lane = tid & 31;
    const int jgrp = blockIdx.x >> 1;
    const int bh   = blockIdx.x & 1;
    const int j0   = jgrp * 8;
    unsigned* myflag = &g_qf[(bh * 4 + (jgrp >> 4)) * 32];

    // Resident recurrent W tiles (hi + lo), padded rows.
    {
        uint4* dst = (uint4*)smc;
        #pragma unroll 2
        for (int s = 0; s < 2; s++) {
            const uint4* src = (const uint4*)(wt + (size_t)s * 1048576 + (size_t)jgrp * 16384);
            uint4* d = dst + s * (WBLK / 16);
            for (int i = tid; i < 2048; i += 256) {
                int row = i >> 6, c = i & 63;
                d[row * 65 + c] = __ldg(src + i);
            }
        }
        if (fuse) {
            uint4* dst2 = (uint4*)(smc + OFF_W2);
            #pragma unroll 2
            for (int s = 0; s < 2; s++) {
                const uint4* src = (const uint4*)(w2t + (size_t)s * 1048576 + (size_t)jgrp * 16384);
                uint4* d = dst2 + s * (WBLK / 16);
                for (int i = tid; i < 2048; i += 256) {
                    int row = i >> 6, c = i & 63;
                    d[row * 65 + c] = __ldg(src + i);
                }
            }
        }
    }

    const int arow = lane & 15;
    const uint32_t akoff = (lane >> 4) * 16;
    const int brow = lane & 7;
    const uint32_t bkoff = ((lane >> 3) & 1) * 16;
    const int m0 = (wid & 1) * 16;
    const int n0 = (wid >> 1) * 8;

    const uint32_t aHi0 = smb + OFF_W + (uint32_t)(m0 + arow) * (PITCH * 2) + akoff;
    const uint32_t aLo0 = aHi0 + WBLK;
    const uint32_t a2Hi0 = smb + OFF_W2 + (uint32_t)(m0 + arow) * (PITCH * 2) + akoff;
    const uint32_t a2Lo0 = a2Hi0 + WBLK;
    const uint32_t bHi0 = smb + OFF_H + (uint32_t)(n0 + brow) * (PITCH * 2) + bkoff;
    const uint32_t bLo0 = bHi0 + WBLK;

    // xg2 fragment bookkeeping (fuse): rows rA=m0+(lane>>2), rB=rA+8.
    const int rA = m0 + (lane >> 2);
    const int rB = rA + 8;
    const int iA = (rA & 3) * 512 + j0 + (rA >> 2);
    const int iB = (rB & 3) * 512 + j0 + (rB >> 2);
    const int colb = n0 + (lane & 3) * 2;
    float bzA = 0.f, bzB = 0.f;
    if (fuse) { bzA = g_b2[iA]; bzB = g_b2[iB]; }

    const int u  = tid & 7;
    const int b  = tid >> 3;
    const int gb = bh * 32 + b;
    float c = 0.0f;

    for (int t = 0; t < TT; t++) {
        // xg prefetch first (DRAM latency overlapped with polls).
        float xv0 = __ldg(&xg[((size_t)t * BB + gb) * GG +        j0 + u]);
        float xv1 = __ldg(&xg[((size_t)t * BB + gb) * GG +  512 + j0 + u]);
        float xv2 = __ldg(&xg[((size_t)t * BB + gb) * GG + 1024 + j0 + u]);
        float xv3 = __ldg(&xg[((size_t)t * BB + gb) * GG + 1536 + j0 + u]);

        if (t > 0) {
            // Wait for all 4 quartiles of h(t-1) (4 threads poll in parallel).
            if (tid < 4) {
                unsigned target = qbase + 16u * (unsigned)t;
                unsigned* fp = &g_qf[(bh * 4 + tid) * 32];
                unsigned v;
                do { v = ld_acquire(fp); } while ((int)(v - target) < 0);
            }
            __syncthreads();

            // Stage h(t-1) as 4 cp.async chunk groups.
            int par = (t - 1) % 3;
            const __nv_bfloat16* baseH = &g_hb[0][par][bh][0][0];
            const __nv_bfloat16* baseL = &g_hb[1][par][bh][0][0];
            #pragma unroll
            for (int ck = 0; ck < 4; ck++) {
                #pragma unroll
                for (int j = 0; j < 2; j++) {
                    int i = tid * 2 + j;          // 0..511
                    int row = i >> 4, q = i & 15;
                    uint32_t dst = smb + OFF_H + (uint32_t)row * (PITCH * 2)
                                 + (uint32_t)(ck * 16 + q) * 16;
                    CP16(dst, baseH + row * 512 + ck * 128 + q * 8);
                    CP16(dst + WBLK, baseL + row * 512 + ck * 128 + q * 8);
                }
                asm volatile("cp.async.commit_group;");
            }

            // MMA, chunk-pipelined. Gates (d) + fused xg2 (e, bias-initialized).
            float d0 = 0.f, d1 = 0.f, d2 = 0.f, d3 = 0.f;
            float e0 = bzA, e1 = bzA, e2 = bzB, e3 = bzB;
            #pragma unroll
            for (int ck = 0; ck < 4; ck++) {
                if (ck == 0)      asm volatile("cp.async.wait_group 3;");
                else if (ck == 1) asm volatile("cp.async.wait_group 2;");
                else if (ck == 2) asm volatile("cp.async.wait_group 1;");
                else              asm volatile("cp.async.wait_group 0;");
                __syncthreads();
                #pragma unroll
                for (int ks = 0; ks < 8; ks++) {
                    uint32_t ko = (uint32_t)(ck * 8 + ks) * 32;
                    uint32_t ah0, ah1, ah2, ah3, al0, al1, al2, al3;
                    uint32_t bhr0, bhr1, blr0, blr1;
                    LDSM_X4(ah0, ah1, ah2, ah3, aHi0 + ko);
                    LDSM_X4(al0, al1, al2, al3, aLo0 + ko);
                    LDSM_X2(bhr0, bhr1, bHi0 + ko);
                    LDSM_X2(blr0, blr1, bLo0 + ko);
                    MMA_BF16(d0, d1, d2, d3, ah0, ah1, ah2, ah3, bhr0, bhr1);
                    MMA_BF16(d0, d1, d2, d3, ah0, ah1, ah2, ah3, blr0, blr1);
                    MMA_BF16(d0, d1, d2, d3, al0, al1, al2, al3, bhr0, bhr1);
                    if (fuse) {
                        uint32_t ch0, ch1, ch2, ch3, cl0, cl1, cl2, cl3;
                        LDSM_X4(ch0, ch1, ch2, ch3, a2Hi0 + ko);
                        LDSM_X4(cl0, cl1, cl2, cl3, a2Lo0 + ko);
                        MMA_BF16(e0, e1, e2, e3, ch0, ch1, ch2, ch3, bhr0, bhr1);
                        MMA_BF16(e0, e1, e2, e3, ch0, ch1, ch2, ch3, blr0, blr1);
                        MMA_BF16(e0, e1, e2, e3, cl0, cl1, cl2, cl3, bhr0, bhr1);
                    }
                }
            }
            if (fuse) {   // publish xg2(t-1)
                size_t tb = (size_t)(t - 1) * BB * GG;
                xg2[tb + (size_t)(bh * 32 + colb) * GG + iA]     = e0;
                xg2[tb + (size_t)(bh * 32 + colb + 1) * GG + iA] = e1;
                xg2[tb + (size_t)(bh * 32 + colb) * GG + iB]     = e2;
                xg2[tb + (size_t)(bh * 32 + colb + 1) * GG + iB] = e3;
            }
            {
                int gid = lane >> 2, tig = lane & 3;
                int row = m0 + gid, col = n0 + tig * 2;
                sD[row * 33 + col]           = d0;
                sD[row * 33 + col + 1]       = d1;
                sD[(row + 8) * 33 + col]     = d2;
                sD[(row + 8) * 33 + col + 1] = d3;
            }
            __syncthreads();
        }

        // Fused pointwise: gates of unit u, batch b (tile row = u*4+g).
        {
            float p0 = xv0, p1 = xv1, p2 = xv2, p3 = xv3;
            if (t > 0) {
                p0 += sD[(u * 4 + 0) * 33 + b];
                p1 += sD[(u * 4 + 1) * 33 + b];
                p2 += sD[(u * 4 + 2) * 33 + b];
                p3 += sD[(u * 4 + 3) * 33 + b];
            }
            float gi = sigm_f(p0);
            float gf = sigm_f(p1);
            float gz = tanh_f(p2);
            float go = sigm_f(p3);
            c = gf * c + gi * gz;
            float hv = go * tanh_f(c);

            __nv_bfloat16 hi = __float2bfloat16(hv);
            __nv_bfloat16 lo = __float2bfloat16(hv - __bfloat162float(hi));
            int par = t % 3;
            g_hb[0][par][bh][b][j0 + u] = hi;
            g_hb[1][par][bh][b][j0 + u] = lo;
            if (isL2) H[((size_t)t * BB + gb) * HH + j0 + u] = hv;   // out_proj input
        }

        // Publish: this CTA's 8 units of h(t) are visible (release-cumulative
        // after __syncthreads).
        __syncthreads();
        if (tid == 0) atom_add_release(myflag);
    }

    // Epilogue (fuse): xg2(TT-1) from h(TT-1).
    if (fuse) {
        if (tid < 4) {
            unsigned target = qbase + 16u * (unsigned)TT;
            unsigned* fp = &g_qf[(bh * 4 + tid) * 32];
            unsigned v;
            do { v = ld_acquire(fp); } while ((int)(v - target) < 0);
        }
        __syncthreads();
        int par = (TT - 1) % 3;
        const __nv_bfloat16* baseH = &g_hb[0][par][bh][0][0];
        const __nv_bfloat16* baseL = &g_hb[1][par][bh][0][0];
        #pragma unroll
        for (int ck = 0; ck < 4; ck++) {
            #pragma unroll
            for (int j = 0; j < 2; j++) {
                int i = tid * 2 + j;
                int row = i >> 4, q = i & 15;
                uint32_t dst = smb + OFF_H + (uint32_t)row * (PITCH * 2)
                             + (uint32_t)(ck * 16 + q) * 16;
                CP16(dst, baseH + row * 512 + ck * 128 + q * 8);
                CP16(dst + WBLK, baseL + row * 512 + ck * 128 + q * 8);
            }
        }
        asm volatile("cp.async.commit_group;");
        asm volatile("cp.async.wait_group 0;");
        __syncthreads();

        float e0 = bzA, e1 = bzA, e2 = bzB, e3 = bzB;
        #pragma unroll 8
        for (int ks = 0; ks < 32; ks++) {
            uint32_t ko = (uint32_t)ks * 32;
            uint32_t ch0, ch1, ch2, ch3, cl0, cl1, cl2, cl3;
            uint32_t bhr0, bhr1, blr0, blr1;
            LDSM_X4(ch0, ch1, ch2, ch3, a2Hi0 + ko);
            LDSM_X4(cl0, cl1, cl2, cl3, a2Lo0 + ko);
            LDSM_X2(bhr0, bhr1, bHi0 + ko);
            LDSM_X2(blr0, blr1, bLo0 + ko);
            MMA_BF16(e0, e1, e2, e3, ch0, ch1, ch2, ch3, bhr0, bhr1);
            MMA_BF16(e0, e1, e2, e3, ch0, ch1, ch2, ch3, blr0, blr1);
            MMA_BF16(e0, e1, e2, e3, cl0, cl1, cl2, cl3, bhr0, bhr1);
        }
        size_t tb = (size_t)(TT - 1) * BB * GG;
        xg2[tb + (size_t)(bh * 32 + colb) * GG + iA]     = e0;
        xg2[tb + (size_t)(bh * 32 + colb + 1) * GG + iA] = e1;
        xg2[tb + (size_t)(bh * 32 + colb) * GG + iB]     = e2;
        xg2[tb + (size_t)(bh * 32 + colb + 1) * GG + iB] = e3;
    }
}

// ---------------------------------------------------------------------------
// Output head.
// ---------------------------------------------------------------------------
__global__ __launch_bounds__(256) void out_proj(
    const float* __restrict__ H2, const float* __restrict__ Wout,
    const float* __restrict__ bout, float* __restrict__ out)
{
    int w = (blockIdx.x * blockDim.x + threadIdx.x) >> 5;
    int lane = threadIdx.x & 31;
    if (w >= TT * BB) return;
    const float4* h  = (const float4*)(H2 + (size_t)w * HH);
    const float4* wv = (const float4*)Wout;
    float acc = 0.0f;
    #pragma unroll
    for (int i = lane; i < 128; i += 32) {
        float4 a = __ldg(h + i);
        float4 bb = __ldg(wv + i);
        acc += a.x*bb.x + a.y*bb.y + a.z*bb.z + a.w*bb.w;
    }
    #pragma unroll
    for (int off = 16; off; off >>= 1) acc += __shfl_xor_sync(0xffffffffu, acc, off);
    if (lane == 0) out[w] = 1.0f / (1.0f + expf(-(acc + __ldg(bout))));
}

// ---------------------------------------------------------------------------
extern "C" void kernel_launch(void* const* d_in, const int* in_sizes, int n_in,
                              void* d_out, int out_size)
{
    const float* x     = (const float*)d_in[0];
    const float* Wih1  = (const float*)d_in[1];
    const float* Whh1  = (const float*)d_in[2];
    const float* bih1  = (const float*)d_in[3];
    const float* bhh1  = (const float*)d_in[4];
    const float* Wih2  = (const float*)d_in[5];
    const float* Whh2  = (const float*)d_in[6];
    const float* bih2  = (const float*)d_in[7];
    const float* bhh2  = (const float*)d_in[8];
    const float* Wout  = (const float*)d_in[9];
    const float* bout  = (const float*)d_in[10];
    float* out = (float*)d_out;

    void *xg_p, *xg2_p, *h2_p, *wA_p, *wB_p, *wC_p;
    cudaGetSymbolAddress(&xg_p, g_xg);
    cudaGetSymbolAddress(&xg2_p, g_xg2);
    cudaGetSymbolAddress(&h2_p, g_h2);
    cudaGetSymbolAddress(&wA_p, g_wA);
    cudaGetSymbolAddress(&wB_p, g_wB);
    cudaGetSymbolAddress(&wC_p, g_wC);
    float* xg  = (float*)xg_p;
    float* xg2 = (float*)xg2_p;
    float* h2  = (float*)h2_p;
    __nv_bfloat16* wA = (__nv_bfloat16*)wA_p;
    __nv_bfloat16* wB = (__nv_bfloat16*)wB_p;
    __nv_bfloat16* wC = (__nv_bfloat16*)wC_p;

    cudaFuncSetAttribute(lstm_rec, cudaFuncAttributeMaxDynamicSharedMemorySize, REC_SMEM_F);
    cudaFuncSetAttribute(gemm_mma, cudaFuncAttributeMaxDynamicSharedMemorySize, GSMEM);

    // Preps (prep_a also resets quartile counters each replay).
    prep_a<<<(TT * BB * 256 + 255) / 256, 256>>>(x, TT * BB * 256);
    prep_wih<<<2048, 256>>>(Wih1, 256);
    prep_wsplit<<<2048, 256>>>(Whh1, wA);
    prep_wsplit<<<2048, 256>>>(Whh2, wB);
    prep_wsplit<<<2048, 256>>>(Wih2, wC);
    prep_b2<<<8, 256>>>(bih2, bhh2);

    // Layer-1 input GEMM.
    dim3 ggrid(16, 1024);
    gemm_mma<<<ggrid, 256, GSMEM>>>(bih1, bhh1, xg, 256);

    // Layer 1 recurrence + fused layer-2 input GEMM (writes g_xg2).
    lstm_rec<<<NCTA, 256, REC_SMEM_F>>>(wA, wC, xg, xg2, h2, 0, 1, 0u);
    // Layer 2 recurrence (reads g_xg2 with biases already folded in).
    lstm_rec<<<NCTA, 256, REC_SMEM>>>(wB, wC, xg2, xg2, h2, 1, 0, 16u * TT);

    // Head.
    out_proj<<<(TT * BB * 32 + 255) / 256, 256>>>(h2, Wout, bout, out);
}

// round 16
// speedup vs baseline: 1.6237x; 1.1254x over previous
#include <cuda_runtime.h>
#include <cuda_bf16.h>
#include <math.h>
#include <stdint.h>

#define TT 2048
#define BB 64
#define HH 512
#define GG 2048

typedef unsigned long long u64;

// Scratch (module-load allocated).
__device__ float g_xg[268435456];                    // [T][B][4H] f32 (reused per layer)
__device__ float g_h2[67108864];                     // layer-2 H (head input)
__device__ __align__(16) __nv_bfloat16 g_ah[67108864];  // A image hi (x-split / h1-split)
__device__ __align__(16) __nv_bfloat16 g_al[67108864];  // A image lo
__device__ __align__(16) __nv_bfloat16 g_wih_h[1048576]; // W_ih hi [2048][512]
__device__ __align__(16) __nv_bfloat16 g_wih_l[1048576];
__device__ __align__(16) __nv_bfloat16 g_wb[2][64][32][512];      // [split][jgrp][row][k]
__device__ __align__(16) __nv_bfloat16 g_hb[2][3][2][32][512];    // [split][par3][bh][b][j]
__device__ unsigned g_qf[8 * 32];                    // quartile counters (128B apart)

__device__ __forceinline__ float sigm_f(float x) {
    return __fdividef(1.0f, 1.0f + __expf(-x));
}
__device__ __forceinline__ float tanh_f(float x) {
    float ax = fabsf(x);
    float e = __expf(-2.0f * ax);
    float r = __fdividef(1.0f - e, 1.0f + e);
    return copysignf(r, x);
}
__device__ __forceinline__ uint32_t smem_u32(const void* p) {
    uint32_t a;
    asm("{ .reg .u64 t; cvta.to.shared.u64 t, %1; cvt.u32.u64 %0, t; }" : "=r"(a) : "l"(p));
    return a;
}
__device__ __forceinline__ void atom_add_release(unsigned* p) {
    unsigned o;
    asm volatile("atom.acq_rel.gpu.global.add.u32 %0, [%1], %2;"
                 : "=r"(o) : "l"(p), "r"(1u) : "memory");
}
__device__ __forceinline__ unsigned ld_acquire(unsigned* p) {
    unsigned v;
    asm volatile("ld.acquire.gpu.global.u32 %0, [%1];" : "=r"(v) : "l"(p) : "memory");
    return v;
}

#define LDSM_X4(r0, r1, r2, r3, addr) \
    asm volatile("ldmatrix.sync.aligned.m8n8.x4.shared.b16 {%0,%1,%2,%3}, [%4];" \
        : "=r"(r0), "=r"(r1), "=r"(r2), "=r"(r3) : "r"(addr))
#define LDSM_X2(r0, r1, addr) \
    asm volatile("ldmatrix.sync.aligned.m8n8.x2.shared.b16 {%0,%1}, [%2];" \
        : "=r"(r0), "=r"(r1) : "r"(addr))
#define MMA_BF16(d0, d1, d2, d3, a0, a1, a2, a3, b0, b1) \
    asm volatile("mma.sync.aligned.m16n8k16.row.col.f32.bf16.bf16.f32 " \
        "{%0,%1,%2,%3}, {%4,%5,%6,%7}, {%8,%9}, {%0,%1,%2,%3};" \
        : "+f"(d0), "+f"(d1), "+f"(d2), "+f"(d3) \
        : "r"(a0), "r"(a1), "r"(a2), "r"(a3), "r"(b0), "r"(b1))
#define CP16(dst, src) \
    asm volatile("cp.async.cg.shared.global [%0], [%1], 16;" :: "r"(dst), "l"(src))

// ---------------------------------------------------------------------------
// prep_a: split f32 array into bf16 hi/lo images; resets the 8 quartile
// counters (block 0) so every graph replay starts from a clean sync state.
// ---------------------------------------------------------------------------
__global__ __launch_bounds__(256) void prep_a(const float* __restrict__ src, int total)
{
    if (blockIdx.x == 0 && threadIdx.x < 8) g_qf[threadIdx.x * 32] = 0;
    int idx = blockIdx.x * 256 + threadIdx.x;
    if (idx >= total) return;
    float v = src[idx];
    __nv_bfloat16 h = __float2bfloat16(v);
    g_ah[idx] = h;
    g_al[idx] = __float2bfloat16(v - __bfloat162float(h));
}

// ---------------------------------------------------------------------------
// prep_wih: split W_ih [2048][K] f32 into bf16 hi/lo at fixed pitch 512.
// ---------------------------------------------------------------------------
__global__ __launch_bounds__(256) void prep_wih(const float* __restrict__ W, int K)
{
    int idx = blockIdx.x * 256 + threadIdx.x;
    int n = idx / K;
    int k = idx - n * K;
    float v = W[idx];
    __nv_bfloat16 h = __float2bfloat16(v);
    g_wih_h[n * 512 + k] = h;
    g_wih_l[n * 512 + k] = __float2bfloat16(v - __bfloat162float(h));
}

// ---------------------------------------------------------------------------
// gemm_mma: C[M x 2048] = A[M x K]*W[2048 x K]^T + bi + bh (3-split bf16 mma).
// CTA tile 128x128, 8 warps (64x32), K-chunk 32, cp.async 2-stage. (R9)
// ---------------------------------------------------------------------------
#define KC 32
#define APB 80
#define REGB (128 * APB)
#define STGB (4 * REGB)
#define GSMEM (2 * STGB)

__global__ __launch_bounds__(256) void gemm_mma(
    const float* __restrict__ bi, const float* __restrict__ bh,
    float* __restrict__ C, int K)
{
    extern __shared__ __align__(16) char gsm[];
    const uint32_t smb = smem_u32(gsm);
    const int tid = threadIdx.x;
    const int wid = tid >> 5, lane = tid & 31;
    const int n0 = blockIdx.x * 128;
    const int m0 = blockIdx.y * 128;
    const int wm = (wid & 1) * 64;
    const int wn = (wid >> 1) * 32;

    auto load_chunk = [&](int c, int s) {
        int kb = c * KC;
        uint32_t base = smb + s * STGB;
        #pragma unroll
        for (int j = 0; j < 8; j++) {
            int u = tid + j * 256;
            int r = u >> 9;
            int e = u & 511;
            int row = e >> 2, q = e & 3;
            const __nv_bfloat16* src;
            if (r == 0)      src = g_ah + (size_t)(m0 + row) * K + kb + q * 8;
            else if (r == 1) src = g_al + (size_t)(m0 + row) * K + kb + q * 8;
            else if (r == 2) src = g_wih_h + (size_t)(n0 + row) * 512 + kb + q * 8;
            else             src = g_wih_l + (size_t)(n0 + row) * 512 + kb + q * 8;
            CP16(base + r * REGB + row * APB + q * 16, src);
        }
        asm volatile("cp.async.commit_group;");
    };

    float acc[4][4][4];
    #pragma unroll
    for (int a = 0; a < 4; a++)
        #pragma unroll
        for (int b = 0; b < 4; b++)
            #pragma unroll
            for (int cix = 0; cix < 4; cix++) acc[a][b][cix] = 0.0f;

    const int NC = K / KC;
    load_chunk(0, 0);
    for (int c = 0; c < NC; c++) {
        if (c + 1 < NC) {
            load_chunk(c + 1, (c + 1) & 1);
            asm volatile("cp.async.wait_group 1;");
        } else {
            asm volatile("cp.async.wait_group 0;");
        }
        __syncthreads();
        uint32_t st = smb + (c & 1) * STGB;
        #pragma unroll
        for (int ks = 0; ks < 2; ks++) {
            uint32_t ko = ks * 32;
            uint32_t Ah[4][4], Al[4][4], Bh[4][2], Bl[4][2];
            #pragma unroll
            for (int f = 0; f < 4; f++) {
                uint32_t ar = st + (uint32_t)(wm + f * 16 + (lane & 15)) * APB
                            + ((lane >> 4) * 16) + ko;
                LDSM_X4(Ah[f][0], Ah[f][1], Ah[f][2], Ah[f][3], ar);
                LDSM_X4(Al[f][0], Al[f][1], Al[f][2], Al[f][3], ar + REGB);
                uint32_t br = st + 2 * REGB + (uint32_t)(wn + f * 8 + (lane & 7)) * APB
                            + (((lane >> 3) & 1) * 16) + ko;
                LDSM_X2(Bh[f][0], Bh[f][1], br);
                LDSM_X2(Bl[f][0], Bl[f][1], br + REGB);
            }
            #pragma unroll
            for (int mf = 0; mf < 4; mf++)
                #pragma unroll
                for (int nf = 0; nf < 4; nf++) {
                    MMA_BF16(acc[mf][nf][0], acc[mf][nf][1], acc[mf][nf][2], acc[mf][nf][3],
                             Ah[mf][0], Ah[mf][1], Ah[mf][2], Ah[mf][3], Bh[nf][0], Bh[nf][1]);
                    MMA_BF16(acc[mf][nf][0], acc[mf][nf][1], acc[mf][nf][2], acc[mf][nf][3],
                             Ah[mf][0], Ah[mf][1], Ah[mf][2], Ah[mf][3], Bl[nf][0], Bl[nf][1]);
                    MMA_BF16(acc[mf][nf][0], acc[mf][nf][1], acc[mf][nf][2], acc[mf][nf][3],
                             Al[mf][0], Al[mf][1], Al[mf][2], Al[mf][3], Bh[nf][0], Bh[nf][1]);
                }
        }
        __syncthreads();
    }

    #pragma unroll
    for (int nf = 0; nf < 4; nf++) {
        int n = n0 + wn + nf * 8 + (lane & 3) * 2;
        float b0 = __ldg(&bi[n]) + __ldg(&bh[n]);
        float b1 = __ldg(&bi[n + 1]) + __ldg(&bh[n + 1]);
        #pragma unroll
        for (int mf = 0; mf < 4; mf++) {
            int m = m0 + wm + mf * 16 + (lane >> 2);
            *(float2*)&C[(size_t)m * GG + n] =
                make_float2(acc[mf][nf][0] + b0, acc[mf][nf][1] + b1);
            *(float2*)&C[(size_t)(m + 8) * GG + n] =
                make_float2(acc[mf][nf][2] + b0, acc[mf][nf][3] + b1);
        }
    }
}

// ---------------------------------------------------------------------------
// prep_w: split Whh into bf16 hi/lo with gate-interleaved row ordering.
// ---------------------------------------------------------------------------
__global__ __launch_bounds__(256) void prep_w(const float* __restrict__ Whh)
{
    int idx  = blockIdx.x * 256 + threadIdx.x;
    int jgrp = idx >> 13;
    int r    = (idx >> 8) & 31;
    int k    = (idx & 255) * 2;
    int wrow = (r & 3) * 512 + jgrp * 8 + (r >> 2);

    float v0 = __ldg(&Whh[(size_t)wrow * HH + k]);
    float v1 = __ldg(&Whh[(size_t)wrow * HH + k + 1]);
    __nv_bfloat16 h0 = __float2bfloat16(v0);
    __nv_bfloat16 h1 = __float2bfloat16(v1);
    g_wb[0][jgrp][r][k]     = h0;
    g_wb[0][jgrp][r][k + 1] = h1;
    g_wb[1][jgrp][r][k]     = __float2bfloat16(v0 - __bfloat162float(h0));
    g_wb[1][jgrp][r][k + 1] = __float2bfloat16(v1 - __bfloat162float(h1));
}

// ---------------------------------------------------------------------------
// Persistent warp-MMA recurrence (R11 protocol verbatim) with REGISTER-
// RESIDENT W fragments: 8 warps retiled 2m x 2n x 2k (warp = 16m x 16n x
// 256k). A fragments preloaded ONCE before the t-loop (W never changes),
// eliminating 2/3 of per-step LDSM crossbar traffic. K-halves reduced via
// sD (+=). 128 CTAs: jgrp(64) x bh(2), 256 threads.
// ---------------------------------------------------------------------------
#define NCTA 128
#define PITCH 520
#define WBLK (32 * PITCH * 2)
#define OFF_W 0
#define OFF_H (2 * WBLK)
#define OFF_D (4 * WBLK)
#define REC_SMEM (OFF_D + 32 * 33 * 4)

__global__ __launch_bounds__(256, 1) void lstm_rec(
    const float* __restrict__ xg, float* __restrict__ H, int isL2, unsigned qbase)
{
    extern __shared__ char smc[];
    const uint32_t smb = smem_u32(smc);
    float* sD = (float*)(smc + OFF_D);

    const int tid  = threadIdx.x;
    const int wid  = tid >> 5;
    const int lane = tid & 31;
    const int jgrp = blockIdx.x >> 1;
    const int bh   = blockIdx.x & 1;
    const int j0   = jgrp * 8;
    unsigned* myflag = &g_qf[(bh * 4 + (jgrp >> 4)) * 32];

    // Resident W tiles (hi + lo), padded rows.
    {
        uint4* dst = (uint4*)smc;
        #pragma unroll 2
        for (int s = 0; s < 2; s++) {
            const uint4* src = (const uint4*)&g_wb[s][jgrp][0][0];
            uint4* d = dst + s * (WBLK / 16);
            for (int i = tid; i < 2048; i += 256) {
                int row = i >> 6, c = i & 63;
                d[row * 65 + c] = __ldg(src + i);
            }
        }
    }
    __syncthreads();

    // Warp retiling: 2m x 2n x 2k.
    const int mh = wid & 1, nh = (wid >> 1) & 1, kh = wid >> 2;
    const int m0 = mh * 16, n0 = nh * 16;

    // Preload A (W) fragments ONCE: Af[split][16 ksteps of this k-half][4].
    const uint32_t aBase = smb + OFF_W + (uint32_t)(m0 + (lane & 15)) * (PITCH * 2)
                         + ((lane >> 4) * 16);
    uint32_t Af[2][16][4];
    #pragma unroll
    for (int s = 0; s < 2; s++)
        #pragma unroll
        for (int ks = 0; ks < 16; ks++)
            LDSM_X4(Af[s][ks][0], Af[s][ks][1], Af[s][ks][2], Af[s][ks][3],
                    aBase + (uint32_t)s * WBLK + (uint32_t)(kh * 16 + ks) * 32);

    // B (h) base: x4 covers 16 batch cols (two n8 frags).
    const uint32_t bB0 = smb + OFF_H
        + (uint32_t)(n0 + (lane & 7) + ((lane >> 4) << 3)) * (PITCH * 2)
        + (((lane >> 3) & 1) * 16);

    const int u  = tid & 7;
    const int b  = tid >> 3;
    const int gb = bh * 32 + b;
    float c = 0.0f;

    for (int t = 0; t < TT; t++) {
        // xg prefetch first (DRAM latency overlapped with polls).
        float xv0 = __ldg(&xg[((size_t)t * BB + gb) * GG +        j0 + u]);
        float xv1 = __ldg(&xg[((size_t)t * BB + gb) * GG +  512 + j0 + u]);
        float xv2 = __ldg(&xg[((size_t)t * BB + gb) * GG + 1024 + j0 + u]);
        float xv3 = __ldg(&xg[((size_t)t * BB + gb) * GG + 1536 + j0 + u]);

        if (t > 0) {
            // Wait for all 4 quartiles of h(t-1) (4 threads poll in parallel).
            if (tid < 4) {
                unsigned target = qbase + 16u * (unsigned)t;
                unsigned* fp = &g_qf[(bh * 4 + tid) * 32];
                unsigned v;
                do { v = ld_acquire(fp); } while ((int)(v - target) < 0);
            }
            __syncthreads();

            // Stage h(t-1) as 4 cp.async chunk groups.
            int par = (t - 1) % 3;
            const __nv_bfloat16* baseH = &g_hb[0][par][bh][0][0];
            const __nv_bfloat16* baseL = &g_hb[1][par][bh][0][0];
            #pragma unroll
            for (int ck = 0; ck < 4; ck++) {
                #pragma unroll
                for (int j = 0; j < 2; j++) {
                    int i = tid * 2 + j;          // 0..511
                    int row = i >> 4, q = i & 15;
                    uint32_t dst = smb + OFF_H + (uint32_t)row * (PITCH * 2)
                                 + (uint32_t)(ck * 16 + q) * 16;
                    CP16(dst, baseH + row * 512 + ck * 128 + q * 8);
                    CP16(dst + WBLK, baseL + row * 512 + ck * 128 + q * 8);
                }
                asm volatile("cp.async.commit_group;");
            }

            // MMA, chunk-pipelined; warp kh owns chunks 2kh, 2kh+1.
            float dA0=0.f, dA1=0.f, dA2=0.f, dA3=0.f;
            float dB0=0.f, dB1=0.f, dB2=0.f, dB3=0.f;
            #pragma unroll
            for (int ck = 0; ck < 4; ck++) {
                if (ck == 0)      asm volatile("cp.async.wait_group 3;");
                else if (ck == 1) asm volatile("cp.async.wait_group 2;");
                else if (ck == 2) asm volatile("cp.async.wait_group 1;");
                else              asm volatile("cp.async.wait_group 0;");
                __syncthreads();
                if ((ck >> 1) == kh) {
                    #pragma unroll
                    for (int ks = 0; ks < 8; ks++) {
                        uint32_t ko = (uint32_t)(ck * 8 + ks) * 32;
                        uint32_t bh0, bh1, bh2, bh3, bl0, bl1, bl2, bl3;
                        LDSM_X4(bh0, bh1, bh2, bh3, bB0 + ko);
                        LDSM_X4(bl0, bl1, bl2, bl3, bB0 + WBLK + ko);
                        const int ls = (ck & 1) * 8 + ks;
                        MMA_BF16(dA0, dA1, dA2, dA3,
                                 Af[0][ls][0], Af[0][ls][1], Af[0][ls][2], Af[0][ls][3],
                                 bh0, bh1);
                        MMA_BF16(dB0, dB1, dB2, dB3,
                                 Af[0][ls][0], Af[0][ls][1], Af[0][ls][2], Af[0][ls][3],
                                 bh2, bh3);
                        MMA_BF16(dA0, dA1, dA2, dA3,
                                 Af[0][ls][0], Af[0][ls][1], Af[0][ls][2], Af[0][ls][3],
                                 bl0, bl1);
                        MMA_BF16(dB0, dB1, dB2, dB3,
                                 Af[0][ls][0], Af[0][ls][1], Af[0][ls][2], Af[0][ls][3],
                                 bl2, bl3);
                        MMA_BF16(dA0, dA1, dA2, dA3,
                                 Af[1][ls][0], Af[1][ls][1], Af[1][ls][2], Af[1][ls][3],
                                 bh0, bh1);
                        MMA_BF16(dB0, dB1, dB2, dB3,
                                 Af[1][ls][0], Af[1][ls][1], Af[1][ls][2], Af[1][ls][3],
                                 bh2, bh3);
                    }
                }
            }
            // Reduce K-halves into sD: kh=0 stores, kh=1 accumulates.
            {
                int row  = m0 + (lane >> 2);
                int colA = n0 + (lane & 3) * 2;
                if (kh == 0) {
                    sD[row * 33 + colA]           = dA0;
                    sD[row * 33 + colA + 1]       = dA1;
                    sD[(row + 8) * 33 + colA]     = dA2;
                    sD[(row + 8) * 33 + colA + 1] = dA3;
                    sD[row * 33 + colA + 8]       = dB0;
                    sD[row * 33 + colA + 9]       = dB1;
                    sD[(row + 8) * 33 + colA + 8] = dB2;
                    sD[(row + 8) * 33 + colA + 9] = dB3;
                }
                __syncthreads();
                if (kh == 1) {
                    sD[row * 33 + colA]           += dA0;
                    sD[row * 33 + colA + 1]       += dA1;
                    sD[(row + 8) * 33 + colA]     += dA2;
                    sD[(row + 8) * 33 + colA + 1] += dA3;
                    sD[row * 33 + colA + 8]       += dB0;
                    sD[row * 33 + colA + 9]       += dB1;
                    sD[(row + 8) * 33 + colA + 8] += dB2;
                    sD[(row + 8) * 33 + colA + 9] += dB3;
                }
                __syncthreads();
            }
        }

        // Fused pointwise: gates of unit u, batch b (tile row = u*4+g).
        {
            float p0 = xv0, p1 = xv1, p2 = xv2, p3 = xv3;
            if (t > 0) {
                p0 += sD[(u * 4 + 0) * 33 + b];
                p1 += sD[(u * 4 + 1) * 33 + b];
                p2 += sD[(u * 4 + 2) * 33 + b];
                p3 += sD[(u * 4 + 3) * 33 + b];
            }
            float gi = sigm_f(p0);
            float gf = sigm_f(p1);
            float gz = tanh_f(p2);
            float go = sigm_f(p3);
            c = gf * c + gi * gz;
            float hv = go * tanh_f(c);

            __nv_bfloat16 hi = __float2bfloat16(hv);
            __nv_bfloat16 lo = __float2bfloat16(hv - __bfloat162float(hi));
            int par = t % 3;
            g_hb[0][par][bh][b][j0 + u] = hi;
            g_hb[1][par][bh][b][j0 + u] = lo;
            if (isL2) {
                H[((size_t)t * BB + gb) * HH + j0 + u] = hv;   // out_proj input
            } else {
                size_t aidx = ((size_t)t * BB + gb) * HH + j0 + u;
                g_ah[aidx] = hi;                               // layer-2 GEMM A image
                g_al[aidx] = lo;
            }
        }

        // Publish: this CTA's 8 units of h(t) are visible (release-cumulative
        // after __syncthreads).
        __syncthreads();
        if (tid == 0) atom_add_release(myflag);
    }
}

// ---------------------------------------------------------------------------
// Output head.
// ---------------------------------------------------------------------------
__global__ __launch_bounds__(256) void out_proj(
    const float* __restrict__ H2, const float* __restrict__ Wout,
    const float* __restrict__ bout, float* __restrict__ out)
{
    int w = (blockIdx.x * blockDim.x + threadIdx.x) >> 5;
    int lane = threadIdx.x & 31;
    if (w >= TT * BB) return;
    const float4* h  = (const float4*)(H2 + (size_t)w * HH);
    const float4* wv = (const float4*)Wout;
    float acc = 0.0f;
    #pragma unroll
    for (int i = lane; i < 128; i += 32) {
        float4 a = __ldg(h + i);
        float4 bb = __ldg(wv + i);
        acc += a.x*bb.x + a.y*bb.y + a.z*bb.z + a.w*bb.w;
    }
    #pragma unroll
    for (int off = 16; off; off >>= 1) acc += __shfl_xor_sync(0xffffffffu, acc, off);
    if (lane == 0) out[w] = 1.0f / (1.0f + expf(-(acc + __ldg(bout))));
}

// ---------------------------------------------------------------------------
extern "C" void kernel_launch(void* const* d_in, const int* in_sizes, int n_in,
                              void* d_out, int out_size)
{
    const float* x     = (const float*)d_in[0];
    const float* Wih1  = (const float*)d_in[1];
    const float* Whh1  = (const float*)d_in[2];
    const float* bih1  = (const float*)d_in[3];
    const float* bhh1  = (const float*)d_in[4];
    const float* Wih2  = (const float*)d_in[5];
    const float* Whh2  = (const float*)d_in[6];
    const float* bih2  = (const float*)d_in[7];
    const float* bhh2  = (const float*)d_in[8];
    const float* Wout  = (const float*)d_in[9];
    const float* bout  = (const float*)d_in[10];
    float* out = (float*)d_out;

    void *xg_p, *h2_p;
    cudaGetSymbolAddress(&xg_p, g_xg);
    cudaGetSymbolAddress(&h2_p, g_h2);
    float* xg = (float*)xg_p;
    float* h2 = (float*)h2_p;

    cudaFuncSetAttribute(lstm_rec, cudaFuncAttributeMaxDynamicSharedMemorySize, REC_SMEM);
    cudaFuncSetAttribute(gemm_mma, cudaFuncAttributeMaxDynamicSharedMemorySize, GSMEM);

    dim3 ggrid(16, 1024);   // (N/128, M/128)

    // Layer 1
    prep_a<<<(TT * BB * 256 + 255) / 256, 256>>>(x, TT * BB * 256);  // also resets g_qf
    prep_wih<<<(2048 * 256) / 256, 256>>>(Wih1, 256);
    gemm_mma<<<ggrid, 256, GSMEM>>>(bih1, bhh1, xg, 256);
    prep_w<<<2048, 256>>>(Whh1);
    lstm_rec<<<NCTA, 256, REC_SMEM>>>(xg, h2, 0, 0u);        // writes g_ah/g_al
    // Layer 2 (xg reused); flags continue from 16*TT per quartile
    prep_wih<<<(2048 * 512) / 256, 256>>>(Wih2, 512);
    gemm_mma<<<ggrid, 256, GSMEM>>>(bih2, bhh2, xg, 512);
    prep_w<<<2048, 256>>>(Whh2);
    lstm_rec<<<NCTA, 256, REC_SMEM>>>(xg, h2, 1, 16u * TT);  // writes f32 H
    // Head
    out_proj<<<(TT * BB * 32 + 255) / 256, 256>>>(h2, Wout, bout, out);
}